// round 10
// baseline (speedup 1.0000x reference)
#include <cuda_runtime.h>
#include <cuda_bf16.h>
#include <math.h>
#include <stdint.h>

#define BB 2
#define NQ 2048
#define NK 2048
#define DD 1024
#define HH 16
#define HDIM 64

// Scratch (allocation-free: __device__ globals)
// Q/K/V/O are stored as tf32 bit patterns (uint32_t) — converted at write time.
__device__ uint32_t g_Q[(size_t)BB * NQ * DD];
__device__ uint32_t g_K[(size_t)BB * NK * DD];
__device__ uint32_t g_V[(size_t)BB * NK * DD];
__device__ uint32_t g_O[(size_t)BB * NQ * DD];
// tf32 copies of the fp32 harness inputs
__device__ uint32_t g_Xq[(size_t)BB * NQ * DD];   // q_seq
__device__ uint32_t g_Xkv[(size_t)BB * NK * DD];  // kv_seq
__device__ uint32_t g_Wq[(size_t)DD * DD];
__device__ uint32_t g_Wk[(size_t)DD * DD];
__device__ uint32_t g_Wv[(size_t)DD * DD];
__device__ uint32_t g_Wo[(size_t)DD * DD];

// ---------------------------------------------------------------------------
// helpers
// ---------------------------------------------------------------------------
__device__ __forceinline__ uint32_t f2tf(float x) {
    uint32_t y;
    asm("cvt.rna.tf32.f32 %0, %1;" : "=r"(y) : "f"(x));
    return y;
}

__device__ __forceinline__ void mma8(float c[4], const uint32_t a[4], const uint32_t b[2]) {
    asm volatile(
        "mma.sync.aligned.m16n8k8.row.col.f32.tf32.tf32.f32 "
        "{%0,%1,%2,%3}, {%4,%5,%6,%7}, {%8,%9}, {%0,%1,%2,%3};\n"
        : "+f"(c[0]), "+f"(c[1]), "+f"(c[2]), "+f"(c[3])
        : "r"(a[0]), "r"(a[1]), "r"(a[2]), "r"(a[3]), "r"(b[0]), "r"(b[1]));
}

__device__ __forceinline__ void cpa16(uint32_t dst_smem, const void* src) {
    asm volatile("cp.async.cg.shared.global [%0], [%1], 16;\n" :: "r"(dst_smem), "l"(src));
}
__device__ __forceinline__ void cp_commit() {
    asm volatile("cp.async.commit_group;\n");
}
__device__ __forceinline__ void cp_wait0() { asm volatile("cp.async.wait_group 0;\n"); }
__device__ __forceinline__ void cp_wait1() { asm volatile("cp.async.wait_group 1;\n"); }
__device__ __forceinline__ void cp_wait2() { asm volatile("cp.async.wait_group 2;\n"); }

__device__ __forceinline__ void stcs2(float* p, float a, float b) {
    asm volatile("st.global.cs.v2.f32 [%0], {%1,%2};\n" :: "l"(p), "f"(a), "f"(b));
}

extern __shared__ char smraw[];

// ---------------------------------------------------------------------------
// fp32 -> tf32 bulk converter (vectorized, grid-stride)
// ---------------------------------------------------------------------------
__global__ void cvt_tf32_kernel(const float4* __restrict__ src, uint4* __restrict__ dst,
                                int n4) {
    int i = blockIdx.x * blockDim.x + threadIdx.x;
    if (i < n4) {
        float4 v = src[i];
        uint4 o;
        o.x = f2tf(v.x); o.y = f2tf(v.y); o.z = f2tf(v.z); o.w = f2tf(v.w);
        dst[i] = o;
    }
}

// ---------------------------------------------------------------------------
// Tensor-core GEMM on pre-converted tf32 inputs + optional fused xpos-RoPE.
// 256x128 block tile, k-tile 32, cp.async double buffered, 256 threads,
// 8 warps (4x2), warp tile 64x64. No CVT in the inner loop.
// Output: fp32 (out_tf32=0) or tf32 bits scaled by prescale (out_tf32=1).
// ---------------------------------------------------------------------------
#define GBM 256
#define GBN 128
#define GBK 32
#define GPAD 36
#define GEMM_SMEM ((2 * GBM * GPAD + 2 * GBN * GPAD) * 4)

__global__ void __launch_bounds__(256, 1)
gemm_bias_rope_tc(const uint32_t* __restrict__ X, const uint32_t* __restrict__ W,
                  const float* __restrict__ bias, void* __restrict__ Yout,
                  int M, int N, int K,
                  const float* __restrict__ freqs, float scale_base, float rsign,
                  int do_rope, int out_tf32, float prescale) {
    uint32_t* Xs = (uint32_t*)smraw;           // [2][GBM][GPAD]
    uint32_t* Ws = Xs + 2 * GBM * GPAD;        // [2][GBN][GPAD]

    int tid = threadIdx.x;
    int warp = tid >> 5, lane = tid & 31;
    int g = lane >> 2, tig = lane & 3;
    int wm = warp >> 1, wn = warp & 1;         // 4 x 2 warps
    int row0 = blockIdx.y * GBM, col0 = blockIdx.x * GBN;

    uint32_t xsB = (uint32_t)__cvta_generic_to_shared(Xs);
    uint32_t wsB = (uint32_t)__cvta_generic_to_shared(Ws);

    float acc[4][8][4] = {};

#define GSTAGE(buf, kt)                                                          \
    do {                                                                         \
        _Pragma("unroll")                                                        \
        for (int i = 0; i < 8; i++) {                                            \
            int idx = tid + i * 256;                                             \
            int r = idx >> 3, c4 = (idx & 7) * 4;                                \
            cpa16(xsB + ((buf) * GBM * GPAD + r * GPAD + c4) * 4,                \
                  X + (size_t)(row0 + r) * K + (kt) + c4);                       \
        }                                                                        \
        _Pragma("unroll")                                                        \
        for (int i = 0; i < 4; i++) {                                            \
            int idx = tid + i * 256;                                             \
            int r = idx >> 3, c4 = (idx & 7) * 4;                                \
            cpa16(wsB + ((buf) * GBN * GPAD + r * GPAD + c4) * 4,                \
                  W + (size_t)(col0 + r) * K + (kt) + c4);                       \
        }                                                                        \
        cp_commit();                                                             \
    } while (0)

    GSTAGE(0, 0);
    int T = K / GBK;
    for (int t = 0; t < T; t++) {
        if (t + 1 < T) { GSTAGE((t + 1) & 1, (t + 1) * GBK); cp_wait1(); }
        else           { cp_wait0(); }
        __syncthreads();
        const uint32_t* Xb = Xs + (t & 1) * GBM * GPAD;
        const uint32_t* Wb = Ws + (t & 1) * GBN * GPAD;
#pragma unroll
        for (int ks = 0; ks < 4; ks++) {
            int k0 = ks * 8;
            uint32_t a[4][4], bf[8][2];
#pragma unroll
            for (int mi = 0; mi < 4; mi++) {
                int rb = wm * 64 + mi * 16 + g;
                a[mi][0] = Xb[rb * GPAD + k0 + tig];
                a[mi][1] = Xb[(rb + 8) * GPAD + k0 + tig];
                a[mi][2] = Xb[rb * GPAD + k0 + tig + 4];
                a[mi][3] = Xb[(rb + 8) * GPAD + k0 + tig + 4];
            }
#pragma unroll
            for (int ni = 0; ni < 8; ni++) {
                int cb = wn * 64 + ni * 8 + g;
                bf[ni][0] = Wb[cb * GPAD + k0 + tig];
                bf[ni][1] = Wb[cb * GPAD + k0 + tig + 4];
            }
#pragma unroll
            for (int mi = 0; mi < 4; mi++)
#pragma unroll
                for (int ni = 0; ni < 8; ni++)
                    mma8(acc[mi][ni], a[mi], bf[ni]);
        }
        __syncthreads();
    }
#undef GSTAGE

#pragma unroll
    for (int mi = 0; mi < 4; mi++) {
        int r = row0 + wm * 64 + mi * 16 + g;
#pragma unroll
        for (int ni = 0; ni < 8; ni++) {
            int c = col0 + wn * 64 + ni * 8 + tig * 2;
            float v0 = acc[mi][ni][0] + bias[c];
            float v1 = acc[mi][ni][1] + bias[c + 1];
            float v2 = acc[mi][ni][2] + bias[c];
            float v3 = acc[mi][ni][3] + bias[c + 1];
            if (do_rope) {
                int cd = c & (HDIM - 1);
                float f = freqs[cd >> 1];
                float sv = ((float)cd + 0.4f * (float)HDIM) / (1.4f * (float)HDIM);
                {
                    float n0 = (float)(r & (NQ - 1));
                    float sn, cs; sincosf(n0 * f, &sn, &cs);
                    float scale = powf(sv, (n0 - (float)(NQ / 2)) / scale_base * rsign);
                    float o0 = (v0 * cs - v1 * sn) * scale;
                    float o1 = (v1 * cs + v0 * sn) * scale;
                    v0 = o0; v1 = o1;
                }
                {
                    float n1 = (float)((r + 8) & (NQ - 1));
                    float sn, cs; sincosf(n1 * f, &sn, &cs);
                    float scale = powf(sv, (n1 - (float)(NQ / 2)) / scale_base * rsign);
                    float o2 = (v2 * cs - v3 * sn) * scale;
                    float o3 = (v3 * cs + v2 * sn) * scale;
                    v2 = o2; v3 = o3;
                }
            }
            if (out_tf32) {
                uint32_t* Y = (uint32_t*)Yout;
                uint2 w0 = make_uint2(f2tf(v0 * prescale), f2tf(v1 * prescale));
                uint2 w1 = make_uint2(f2tf(v2 * prescale), f2tf(v3 * prescale));
                *(uint2*)(Y + (size_t)r * N + c) = w0;
                *(uint2*)(Y + (size_t)(r + 8) * N + c) = w1;
            } else {
                float* Y = (float*)Yout;
                *(float2*)(Y + (size_t)r * N + c) = make_float2(v0, v1);
                *(float2*)(Y + (size_t)(r + 8) * N + c) = make_float2(v2, v3);
            }
        }
    }
}

// ---------------------------------------------------------------------------
// Fused attention, 256 threads, Q fragments resident in registers, all
// K/V/Q data PRE-CONVERTED to tf32 — the hot loops issue zero CVT.
// ---------------------------------------------------------------------------
#define APAD 68
#define PPAD 132
#define OQ_W 0
#define OK_W (128 * APAD)
#define OV_W (OK_W + 2 * 128 * APAD)
#define OP_W (OV_W + 128 * APAD)
#define OPART_W (OP_W + 128 * PPAD)
#define ORINV_W (OPART_W + 512)
#define ATTN_SMEM ((ORINV_W + 128) * 4)

__global__ void __launch_bounds__(256, 1)
attn_fused(const uint32_t* __restrict__ Q, const uint32_t* __restrict__ Kg,
           const uint32_t* __restrict__ Vg, float* __restrict__ attn,
           uint32_t* __restrict__ O) {
    uint32_t* smw = (uint32_t*)smraw;
    uint32_t* Qs = smw + OQ_W;              // [128][APAD] tf32 (staging only)
    uint32_t* Ks = smw + OK_W;              // [2][128][APAD] tf32
    uint32_t* Vs = smw + OV_W;              // [128][APAD] tf32
    uint32_t* Ps = smw + OP_W;              // [128][PPAD] tf32
    float* part = (float*)(smw + OPART_W);  // [4][128]
    float* rinv = (float*)(smw + ORINV_W);  // [128]

    int bh = blockIdx.y;
    int b = bh / HH, h = bh % HH;
    int q0 = blockIdx.x * 128;
    const uint32_t* Qb = Q + (size_t)b * NQ * DD + h * HDIM;
    const uint32_t* Kb = Kg + (size_t)b * NK * DD + h * HDIM;
    const uint32_t* Vb = Vg + (size_t)b * NK * DD + h * HDIM;
    float* outP = attn + (size_t)bh * NQ * NK;

    int tid = threadIdx.x;
    int warp = tid >> 5, lane = tid & 31;
    int g = lane >> 2, tig = lane & 3;
    int wm = warp >> 2, wn = warp & 3;      // 2x4 (S): 64x32 warp tiles
    int wm2 = warp >> 1, wn2 = warp & 1;    // 4x2 (PV): 32x32 warp tiles

    uint32_t ksB = (uint32_t)__cvta_generic_to_shared(Ks);
    uint32_t vsB = (uint32_t)__cvta_generic_to_shared(Vs);

#define KSTAGE(buf, kt)                                                          \
    do {                                                                         \
        _Pragma("unroll")                                                        \
        for (int i = 0; i < 8; i++) {                                            \
            int idx = tid + i * 256;                                             \
            int r = idx >> 4, c4 = (idx & 15) * 4;                               \
            cpa16(ksB + ((buf) * 128 * APAD + r * APAD + c4) * 4,                \
                  Kb + (size_t)((kt) * 128 + r) * DD + c4);                      \
        }                                                                        \
        cp_commit();                                                             \
    } while (0)

#define VSTAGE(kt)                                                               \
    do {                                                                         \
        _Pragma("unroll")                                                        \
        for (int i = 0; i < 8; i++) {                                            \
            int idx = tid + i * 256;                                             \
            int r = idx >> 4, c4 = (idx & 15) * 4;                               \
            cpa16(vsB + (r * APAD + c4) * 4,                                     \
                  Vb + (size_t)((kt) * 128 + r) * DD + c4);                      \
        }                                                                        \
        cp_commit();                                                             \
    } while (0)

    // Stage Q tile (already tf32, already pre-scaled by 0.125) and hoist the
    // per-warp fragment set into registers for the whole kernel.
#pragma unroll
    for (int i = 0; i < 8; i++) {
        int idx = tid + i * 256;
        int r = idx >> 4, c = (idx & 15) * 4;
        uint4 v = *(const uint4*)(Qb + (size_t)(q0 + r) * DD + c);
        uint32_t* p = Qs + r * APAD + c;
        p[0] = v.x; p[1] = v.y; p[2] = v.z; p[3] = v.w;
    }
    __syncthreads();

    uint32_t qf[8][4][4];   // [ks][mi][frag] — Q resident
#pragma unroll
    for (int ks = 0; ks < 8; ks++) {
        int k0 = ks * 8;
#pragma unroll
        for (int mi = 0; mi < 4; mi++) {
            int rb = wm * 64 + mi * 16 + g;
            qf[ks][mi][0] = Qs[rb * APAD + k0 + tig];
            qf[ks][mi][1] = Qs[(rb + 8) * APAD + k0 + tig];
            qf[ks][mi][2] = Qs[rb * APAD + k0 + tig + 4];
            qf[ks][mi][3] = Qs[(rb + 8) * APAD + k0 + tig + 4];
        }
    }

    // ---------------- Pass 1: row sums of exp(S) ----------------
    float rs[8] = {};
    KSTAGE(0, 0);
    for (int kt = 0; kt < 16; kt++) {
        if (kt < 15) { KSTAGE((kt + 1) & 1, kt + 1); cp_wait1(); }
        else         { cp_wait0(); }
        __syncthreads();
        const uint32_t* Kbs = Ks + (kt & 1) * 128 * APAD;
#pragma unroll
        for (int half = 0; half < 2; half++) {
            float acc[4][2][4] = {};
#pragma unroll
            for (int ks = 0; ks < 8; ks++) {
                int k0 = ks * 8;
                uint32_t bf[2][2];
#pragma unroll
                for (int ni = 0; ni < 2; ni++) {
                    int cb = wn * 32 + (half * 2 + ni) * 8 + g;
                    bf[ni][0] = Kbs[cb * APAD + k0 + tig];
                    bf[ni][1] = Kbs[cb * APAD + k0 + tig + 4];
                }
#pragma unroll
                for (int mi = 0; mi < 4; mi++)
#pragma unroll
                    for (int ni = 0; ni < 2; ni++)
                        mma8(acc[mi][ni], qf[ks][mi], bf[ni]);
            }
#pragma unroll
            for (int mi = 0; mi < 4; mi++)
#pragma unroll
                for (int ni = 0; ni < 2; ni++) {
                    rs[mi * 2 + 0] += __expf(acc[mi][ni][0]) + __expf(acc[mi][ni][1]);
                    rs[mi * 2 + 1] += __expf(acc[mi][ni][2]) + __expf(acc[mi][ni][3]);
                }
        }
        __syncthreads();
    }
    // Deterministic cross-warp row-sum reduction.
#pragma unroll
    for (int j = 0; j < 8; j++) {
        float v = rs[j];
        v += __shfl_xor_sync(0xffffffffu, v, 1);
        v += __shfl_xor_sync(0xffffffffu, v, 2);
        if (tig == 0)
            part[wn * 128 + wm * 64 + (j >> 1) * 16 + g + (j & 1) * 8] = v;
    }
    __syncthreads();
    if (tid < 128)
        rinv[tid] = 1.0f / (part[tid] + part[128 + tid] + part[256 + tid] + part[384 + tid]);
    __syncthreads();

    // ---------------- Pass 2: P out + P*V ----------------
    float acc_o[2][4][4] = {};
    KSTAGE(0, 0);
    for (int kt = 0; kt < 16; kt++) {
        if (kt < 15) KSTAGE((kt + 1) & 1, kt + 1);
        VSTAGE(kt);
        if (kt < 15) cp_wait2(); else cp_wait1();   // K(kt) ready
        __syncthreads();
        const uint32_t* Kbs = Ks + (kt & 1) * 128 * APAD;
#pragma unroll
        for (int half = 0; half < 2; half++) {
            float acc[4][2][4] = {};
#pragma unroll
            for (int ks = 0; ks < 8; ks++) {
                int k0 = ks * 8;
                uint32_t bf[2][2];
#pragma unroll
                for (int ni = 0; ni < 2; ni++) {
                    int cb = wn * 32 + (half * 2 + ni) * 8 + g;
                    bf[ni][0] = Kbs[cb * APAD + k0 + tig];
                    bf[ni][1] = Kbs[cb * APAD + k0 + tig + 4];
                }
#pragma unroll
                for (int mi = 0; mi < 4; mi++)
#pragma unroll
                    for (int ni = 0; ni < 2; ni++)
                        mma8(acc[mi][ni], qf[ks][mi], bf[ni]);
            }
            // Normalize, emit P to gmem (streaming) and smem (tf32).
#pragma unroll
            for (int mi = 0; mi < 4; mi++) {
                int rl = wm * 64 + mi * 16 + g;
                float ri0 = rinv[rl], ri1 = rinv[rl + 8];
#pragma unroll
                for (int ni = 0; ni < 2; ni++) {
                    int cl = wn * 32 + (half * 2 + ni) * 8 + tig * 2;
                    float p0 = __expf(acc[mi][ni][0]) * ri0;
                    float p1 = __expf(acc[mi][ni][1]) * ri0;
                    float p2 = __expf(acc[mi][ni][2]) * ri1;
                    float p3 = __expf(acc[mi][ni][3]) * ri1;
                    stcs2(outP + (size_t)(q0 + rl) * NK + kt * 128 + cl, p0, p1);
                    stcs2(outP + (size_t)(q0 + rl + 8) * NK + kt * 128 + cl, p2, p3);
                    uint32_t* pp = Ps + rl * PPAD + cl;
                    pp[0] = f2tf(p0); pp[1] = f2tf(p1);
                    uint32_t* pq = Ps + (rl + 8) * PPAD + cl;
                    pq[0] = f2tf(p2); pq[1] = f2tf(p3);
                }
            }
        }
        if (kt < 15) cp_wait1(); else cp_wait0();   // V(kt) ready
        __syncthreads();                            // Ps + Vs visible
        // O += P(128x128) * V(128x64): 4x2 warp grid, 32x32 tiles
#pragma unroll
        for (int ks = 0; ks < 16; ks++) {
            int k0 = ks * 8;
            uint32_t a[2][4], bf[4][2];
#pragma unroll
            for (int mi = 0; mi < 2; mi++) {
                int rb = wm2 * 32 + mi * 16 + g;
                a[mi][0] = Ps[rb * PPAD + k0 + tig];
                a[mi][1] = Ps[(rb + 8) * PPAD + k0 + tig];
                a[mi][2] = Ps[rb * PPAD + k0 + tig + 4];
                a[mi][3] = Ps[(rb + 8) * PPAD + k0 + tig + 4];
            }
#pragma unroll
            for (int ni = 0; ni < 4; ni++) {
                int nb = wn2 * 32 + ni * 8 + g;
                bf[ni][0] = Vs[(k0 + tig) * APAD + nb];
                bf[ni][1] = Vs[(k0 + tig + 4) * APAD + nb];
            }
#pragma unroll
            for (int mi = 0; mi < 2; mi++)
#pragma unroll
                for (int ni = 0; ni < 4; ni++)
                    mma8(acc_o[mi][ni], a[mi], bf[ni]);
        }
        __syncthreads();
    }
#undef KSTAGE
#undef VSTAGE

    // Write O as tf32 bits (consumed by the tf32 out-projection GEMM).
#pragma unroll
    for (int mi = 0; mi < 2; mi++) {
        int r = q0 + wm2 * 32 + mi * 16 + g;
#pragma unroll
        for (int ni = 0; ni < 4; ni++) {
            int c = wn2 * 32 + ni * 8 + tig * 2;
            uint32_t* o0 = O + ((size_t)b * NQ + r) * DD + h * HDIM + c;
            *(uint2*)o0 = make_uint2(f2tf(acc_o[mi][ni][0]), f2tf(acc_o[mi][ni][1]));
            uint32_t* o1 = O + ((size_t)b * NQ + r + 8) * DD + h * HDIM + c;
            *(uint2*)o1 = make_uint2(f2tf(acc_o[mi][ni][2]), f2tf(acc_o[mi][ni][3]));
        }
    }
}

// ---------------------------------------------------------------------------
extern "C" void kernel_launch(void* const* d_in, const int* in_sizes, int n_in,
                              void* d_out, int out_size) {
    const float* q_seq   = (const float*)d_in[0];
    const float* kv_seq  = (const float*)d_in[1];
    const float* Wq      = (const float*)d_in[2];
    const float* bq      = (const float*)d_in[3];
    const float* Wk      = (const float*)d_in[4];
    const float* bk      = (const float*)d_in[5];
    const float* Wv      = (const float*)d_in[6];
    const float* bv      = (const float*)d_in[7];
    const float* Wo      = (const float*)d_in[8];
    const float* bo      = (const float*)d_in[9];
    const float* freqs_q = (const float*)d_in[10];
    const float* freqs_kv= (const float*)d_in[11];

    float* out  = (float*)d_out;
    float* attn = out + (size_t)BB * NQ * DD;

    uint32_t *gQ, *gK, *gV, *gO, *gXq, *gXkv, *gWq, *gWk, *gWv, *gWo;
    cudaGetSymbolAddress((void**)&gQ,  g_Q);
    cudaGetSymbolAddress((void**)&gK,  g_K);
    cudaGetSymbolAddress((void**)&gV,  g_V);
    cudaGetSymbolAddress((void**)&gO,  g_O);
    cudaGetSymbolAddress((void**)&gXq, g_Xq);
    cudaGetSymbolAddress((void**)&gXkv,g_Xkv);
    cudaGetSymbolAddress((void**)&gWq, g_Wq);
    cudaGetSymbolAddress((void**)&gWk, g_Wk);
    cudaGetSymbolAddress((void**)&gWv, g_Wv);
    cudaGetSymbolAddress((void**)&gWo, g_Wo);

    static int attr_done = 0;
    if (!attr_done) {
        cudaFuncSetAttribute(gemm_bias_rope_tc,
                             cudaFuncAttributeMaxDynamicSharedMemorySize, GEMM_SMEM);
        cudaFuncSetAttribute(attn_fused,
                             cudaFuncAttributeMaxDynamicSharedMemorySize, ATTN_SMEM);
        attr_done = 1;
    }

    // Pre-convert all fp32 inputs to tf32 once (bandwidth kernel).
    const int SEQ4 = (BB * NQ * DD) / 4;     // 1,048,576 float4s
    const int W4   = (DD * DD) / 4;          // 262,144
    cvt_tf32_kernel<<<(SEQ4 + 255) / 256, 256>>>((const float4*)q_seq,  (uint4*)gXq,  SEQ4);
    cvt_tf32_kernel<<<(SEQ4 + 255) / 256, 256>>>((const float4*)kv_seq, (uint4*)gXkv, SEQ4);
    cvt_tf32_kernel<<<(W4 + 255) / 256, 256>>>((const float4*)Wq, (uint4*)gWq, W4);
    cvt_tf32_kernel<<<(W4 + 255) / 256, 256>>>((const float4*)Wk, (uint4*)gWk, W4);
    cvt_tf32_kernel<<<(W4 + 255) / 256, 256>>>((const float4*)Wv, (uint4*)gWv, W4);
    cvt_tf32_kernel<<<(W4 + 255) / 256, 256>>>((const float4*)Wo, (uint4*)gWo, W4);

    dim3 gproj(DD / GBN, (BB * NQ) / GBM);   // 8 x 16 = 128 blocks

    // Q: rope(sign +1), output tf32 pre-scaled by 0.125 (exact pow2).
    gemm_bias_rope_tc<<<gproj, 256, GEMM_SMEM>>>(
        gXq, gWq, bq, gQ, BB * NQ, DD, DD, freqs_q, (float)(2 * NQ), 1.0f, 1, 1, 0.125f);
    // K: rope(sign -1), tf32 out.
    gemm_bias_rope_tc<<<gproj, 256, GEMM_SMEM>>>(
        gXkv, gWk, bk, gK, BB * NK, DD, DD, freqs_kv, (float)(2 * NK), -1.0f, 1, 1, 1.0f);
    // V: no rope, tf32 out.
    gemm_bias_rope_tc<<<gproj, 256, GEMM_SMEM>>>(
        gXkv, gWv, bv, gV, BB * NK, DD, DD, nullptr, 1.0f, 0.0f, 0, 1, 1.0f);

    attn_fused<<<dim3(NQ / 128, BB * HH), 256, ATTN_SMEM>>>(gQ, gK, gV, attn, gO);

    // Out-projection: fp32 output.
    gemm_bias_rope_tc<<<gproj, 256, GEMM_SMEM>>>(
        gO, gWo, bo, out, BB * NQ, DD, DD, nullptr, 1.0f, 0.0f, 0, 0, 1.0f);
}

// round 11
// speedup vs baseline: 1.0101x; 1.0101x over previous
#include <cuda_runtime.h>
#include <cuda_bf16.h>
#include <math.h>
#include <stdint.h>

#define BB 2
#define NQ 2048
#define NK 2048
#define DD 1024
#define HH 16
#define HDIM 64

// Scratch (allocation-free: __device__ globals)
// Q/K/V/O stored as tf32 bit patterns (uint32_t) — converted at write time.
__device__ uint32_t g_Q[(size_t)BB * NQ * DD];
__device__ uint32_t g_K[(size_t)BB * NK * DD];
__device__ uint32_t g_V[(size_t)BB * NK * DD];
__device__ uint32_t g_O[(size_t)BB * NQ * DD];
// tf32 copies of the fp32 harness inputs
__device__ uint32_t g_Xq[(size_t)BB * NQ * DD];
__device__ uint32_t g_Xkv[(size_t)BB * NK * DD];
__device__ uint32_t g_Wq[(size_t)DD * DD];
__device__ uint32_t g_Wk[(size_t)DD * DD];
__device__ uint32_t g_Wv[(size_t)DD * DD];
__device__ uint32_t g_Wo[(size_t)DD * DD];

// ---------------------------------------------------------------------------
// helpers
// ---------------------------------------------------------------------------
__device__ __forceinline__ uint32_t f2tf(float x) {
    uint32_t y;
    asm("cvt.rna.tf32.f32 %0, %1;" : "=r"(y) : "f"(x));
    return y;
}

__device__ __forceinline__ void mma8(float c[4], const uint32_t a[4], const uint32_t b[2]) {
    asm volatile(
        "mma.sync.aligned.m16n8k8.row.col.f32.tf32.tf32.f32 "
        "{%0,%1,%2,%3}, {%4,%5,%6,%7}, {%8,%9}, {%0,%1,%2,%3};\n"
        : "+f"(c[0]), "+f"(c[1]), "+f"(c[2]), "+f"(c[3])
        : "r"(a[0]), "r"(a[1]), "r"(a[2]), "r"(a[3]), "r"(b[0]), "r"(b[1]));
}

// ldmatrix: one x4 = full tf32 A-fragment (16x8), one x2 = full B-fragment (8x8).
// Addressing (A, pitch P words, tile at row rb col k0):
//   row = rb + (lane & 15), col = k0 + (lane >> 4) * 4
// Addressing (B, tile rows cb, col k0):
//   row = cb + (lane & 7),  col = k0 + ((lane >> 3) & 1) * 4
__device__ __forceinline__ void ldsm4(uint32_t a[4], uint32_t addr) {
    asm volatile("ldmatrix.sync.aligned.m8n8.x4.shared.b16 {%0,%1,%2,%3}, [%4];"
                 : "=r"(a[0]), "=r"(a[1]), "=r"(a[2]), "=r"(a[3]) : "r"(addr));
}
__device__ __forceinline__ void ldsm2(uint32_t b[2], uint32_t addr) {
    asm volatile("ldmatrix.sync.aligned.m8n8.x2.shared.b16 {%0,%1}, [%2];"
                 : "=r"(b[0]), "=r"(b[1]) : "r"(addr));
}

__device__ __forceinline__ void cpa16(uint32_t dst_smem, const void* src) {
    asm volatile("cp.async.cg.shared.global [%0], [%1], 16;\n" :: "r"(dst_smem), "l"(src));
}
__device__ __forceinline__ void cp_commit() {
    asm volatile("cp.async.commit_group;\n");
}
__device__ __forceinline__ void cp_wait0() { asm volatile("cp.async.wait_group 0;\n"); }
__device__ __forceinline__ void cp_wait1() { asm volatile("cp.async.wait_group 1;\n"); }
__device__ __forceinline__ void cp_wait2() { asm volatile("cp.async.wait_group 2;\n"); }

__device__ __forceinline__ void stcs2(float* p, float a, float b) {
    asm volatile("st.global.cs.v2.f32 [%0], {%1,%2};\n" :: "l"(p), "f"(a), "f"(b));
}

extern __shared__ char smraw[];

// ---------------------------------------------------------------------------
// fp32 -> tf32 bulk converter (vectorized)
// ---------------------------------------------------------------------------
__global__ void cvt_tf32_kernel(const float4* __restrict__ src, uint4* __restrict__ dst,
                                int n4) {
    int i = blockIdx.x * blockDim.x + threadIdx.x;
    if (i < n4) {
        float4 v = src[i];
        uint4 o;
        o.x = f2tf(v.x); o.y = f2tf(v.y); o.z = f2tf(v.z); o.w = f2tf(v.w);
        dst[i] = o;
    }
}

// ---------------------------------------------------------------------------
// Tensor-core GEMM (tf32 inputs) + optional fused xpos-RoPE epilogue.
// 256x128 tile, k-tile 32, cp.async double-buffered, 8 warps 4x2,
// warp tile 64x64. ALL fragment loads via ldmatrix.
// ---------------------------------------------------------------------------
#define GBM 256
#define GBN 128
#define GBK 32
#define GPAD 36
#define GEMM_SMEM ((2 * GBM * GPAD + 2 * GBN * GPAD) * 4)

__global__ void __launch_bounds__(256, 1)
gemm_bias_rope_tc(const uint32_t* __restrict__ X, const uint32_t* __restrict__ W,
                  const float* __restrict__ bias, void* __restrict__ Yout,
                  int M, int N, int K,
                  const float* __restrict__ freqs, float scale_base, float rsign,
                  int do_rope, int out_tf32, float prescale) {
    uint32_t* Xs = (uint32_t*)smraw;           // [2][GBM][GPAD]
    uint32_t* Ws = Xs + 2 * GBM * GPAD;        // [2][GBN][GPAD]

    int tid = threadIdx.x;
    int warp = tid >> 5, lane = tid & 31;
    int g = lane >> 2, tig = lane & 3;
    int wm = warp >> 1, wn = warp & 1;         // 4 x 2 warps
    int row0 = blockIdx.y * GBM, col0 = blockIdx.x * GBN;

    uint32_t xsB = (uint32_t)__cvta_generic_to_shared(Xs);
    uint32_t wsB = (uint32_t)__cvta_generic_to_shared(Ws);

    // ldmatrix per-lane address bases (within buffer 0)
    uint32_t aOff = ((wm * 64 + (lane & 15)) * GPAD + (lane >> 4) * 4) * 4;
    uint32_t bOff = ((wn * 64 + (lane & 7)) * GPAD + ((lane >> 3) & 1) * 4) * 4;

    float acc[4][8][4] = {};

#define GSTAGE(buf, kt)                                                          \
    do {                                                                         \
        _Pragma("unroll")                                                        \
        for (int i = 0; i < 8; i++) {                                            \
            int idx = tid + i * 256;                                             \
            int r = idx >> 3, c4 = (idx & 7) * 4;                                \
            cpa16(xsB + ((buf) * GBM * GPAD + r * GPAD + c4) * 4,                \
                  X + (size_t)(row0 + r) * K + (kt) + c4);                       \
        }                                                                        \
        _Pragma("unroll")                                                        \
        for (int i = 0; i < 4; i++) {                                            \
            int idx = tid + i * 256;                                             \
            int r = idx >> 3, c4 = (idx & 7) * 4;                                \
            cpa16(wsB + ((buf) * GBN * GPAD + r * GPAD + c4) * 4,                \
                  W + (size_t)(col0 + r) * K + (kt) + c4);                       \
        }                                                                        \
        cp_commit();                                                             \
    } while (0)

    GSTAGE(0, 0);
    int T = K / GBK;
    for (int t = 0; t < T; t++) {
        if (t + 1 < T) { GSTAGE((t + 1) & 1, (t + 1) * GBK); cp_wait1(); }
        else           { cp_wait0(); }
        __syncthreads();
        uint32_t xb = xsB + (t & 1) * GBM * GPAD * 4 + aOff;
        uint32_t wb = wsB + (t & 1) * GBN * GPAD * 4 + bOff;
#pragma unroll
        for (int ks = 0; ks < 4; ks++) {
            int k0 = ks * 8;
            uint32_t a[4][4], bf[8][2];
#pragma unroll
            for (int mi = 0; mi < 4; mi++)
                ldsm4(a[mi], xb + (mi * 16 * GPAD + k0) * 4);
#pragma unroll
            for (int ni = 0; ni < 8; ni++)
                ldsm2(bf[ni], wb + (ni * 8 * GPAD + k0) * 4);
#pragma unroll
            for (int mi = 0; mi < 4; mi++)
#pragma unroll
                for (int ni = 0; ni < 8; ni++)
                    mma8(acc[mi][ni], a[mi], bf[ni]);
        }
        __syncthreads();
    }
#undef GSTAGE

#pragma unroll
    for (int mi = 0; mi < 4; mi++) {
        int r = row0 + wm * 64 + mi * 16 + g;
#pragma unroll
        for (int ni = 0; ni < 8; ni++) {
            int c = col0 + wn * 64 + ni * 8 + tig * 2;
            float v0 = acc[mi][ni][0] + bias[c];
            float v1 = acc[mi][ni][1] + bias[c + 1];
            float v2 = acc[mi][ni][2] + bias[c];
            float v3 = acc[mi][ni][3] + bias[c + 1];
            if (do_rope) {
                int cd = c & (HDIM - 1);
                float f = freqs[cd >> 1];
                float sv = ((float)cd + 0.4f * (float)HDIM) / (1.4f * (float)HDIM);
                {
                    float n0 = (float)(r & (NQ - 1));
                    float sn, cs; sincosf(n0 * f, &sn, &cs);
                    float scale = powf(sv, (n0 - (float)(NQ / 2)) / scale_base * rsign);
                    float o0 = (v0 * cs - v1 * sn) * scale;
                    float o1 = (v1 * cs + v0 * sn) * scale;
                    v0 = o0; v1 = o1;
                }
                {
                    float n1 = (float)((r + 8) & (NQ - 1));
                    float sn, cs; sincosf(n1 * f, &sn, &cs);
                    float scale = powf(sv, (n1 - (float)(NQ / 2)) / scale_base * rsign);
                    float o2 = (v2 * cs - v3 * sn) * scale;
                    float o3 = (v3 * cs + v2 * sn) * scale;
                    v2 = o2; v3 = o3;
                }
            }
            if (out_tf32) {
                uint32_t* Y = (uint32_t*)Yout;
                *(uint2*)(Y + (size_t)r * N + c) =
                    make_uint2(f2tf(v0 * prescale), f2tf(v1 * prescale));
                *(uint2*)(Y + (size_t)(r + 8) * N + c) =
                    make_uint2(f2tf(v2 * prescale), f2tf(v3 * prescale));
            } else {
                float* Y = (float*)Yout;
                *(float2*)(Y + (size_t)r * N + c) = make_float2(v0, v1);
                *(float2*)(Y + (size_t)(r + 8) * N + c) = make_float2(v2, v3);
            }
        }
    }
}

// ---------------------------------------------------------------------------
// Fused attention, 256 threads, Q fragments in registers (loaded via
// ldmatrix), all K/Ps fragments via ldmatrix, V B-fragments scalar.
// ---------------------------------------------------------------------------
#define APAD 68
#define PPAD 132
#define OQ_W 0
#define OK_W (128 * APAD)
#define OV_W (OK_W + 2 * 128 * APAD)
#define OP_W (OV_W + 128 * APAD)
#define OPART_W (OP_W + 128 * PPAD)
#define ORINV_W (OPART_W + 512)
#define ATTN_SMEM ((ORINV_W + 128) * 4)

__global__ void __launch_bounds__(256, 1)
attn_fused(const uint32_t* __restrict__ Q, const uint32_t* __restrict__ Kg,
           const uint32_t* __restrict__ Vg, float* __restrict__ attn,
           uint32_t* __restrict__ O) {
    uint32_t* smw = (uint32_t*)smraw;
    uint32_t* Qs = smw + OQ_W;              // [128][APAD] tf32 (staging only)
    uint32_t* Ks = smw + OK_W;              // [2][128][APAD] tf32
    uint32_t* Vs = smw + OV_W;              // [128][APAD] tf32
    uint32_t* Ps = smw + OP_W;              // [128][PPAD] tf32
    float* part = (float*)(smw + OPART_W);  // [4][128]
    float* rinv = (float*)(smw + ORINV_W);  // [128]

    int bh = blockIdx.y;
    int b = bh / HH, h = bh % HH;
    int q0 = blockIdx.x * 128;
    const uint32_t* Qb = Q + (size_t)b * NQ * DD + h * HDIM;
    const uint32_t* Kb = Kg + (size_t)b * NK * DD + h * HDIM;
    const uint32_t* Vb = Vg + (size_t)b * NK * DD + h * HDIM;
    float* outP = attn + (size_t)bh * NQ * NK;

    int tid = threadIdx.x;
    int warp = tid >> 5, lane = tid & 31;
    int g = lane >> 2, tig = lane & 3;
    int wm = warp >> 2, wn = warp & 3;      // 2x4 (S): 64x32 warp tiles
    int wm2 = warp >> 1, wn2 = warp & 1;    // 4x2 (PV): 32x32 warp tiles

    uint32_t qsB = (uint32_t)__cvta_generic_to_shared(Qs);
    uint32_t ksB = (uint32_t)__cvta_generic_to_shared(Ks);
    uint32_t vsB = (uint32_t)__cvta_generic_to_shared(Vs);
    uint32_t psB = (uint32_t)__cvta_generic_to_shared(Ps);

    // ldmatrix per-lane bases
    uint32_t qA = qsB + ((wm * 64 + (lane & 15)) * APAD + (lane >> 4) * 4) * 4;
    uint32_t kB = ((wn * 32 + (lane & 7)) * APAD + ((lane >> 3) & 1) * 4) * 4;
    uint32_t pA = psB + ((wm2 * 32 + (lane & 15)) * PPAD + (lane >> 4) * 4) * 4;

#define KSTAGE(buf, kt)                                                          \
    do {                                                                         \
        _Pragma("unroll")                                                        \
        for (int i = 0; i < 8; i++) {                                            \
            int idx = tid + i * 256;                                             \
            int r = idx >> 4, c4 = (idx & 15) * 4;                               \
            cpa16(ksB + ((buf) * 128 * APAD + r * APAD + c4) * 4,                \
                  Kb + (size_t)((kt) * 128 + r) * DD + c4);                      \
        }                                                                        \
        cp_commit();                                                             \
    } while (0)

#define VSTAGE(kt)                                                               \
    do {                                                                         \
        _Pragma("unroll")                                                        \
        for (int i = 0; i < 8; i++) {                                            \
            int idx = tid + i * 256;                                             \
            int r = idx >> 4, c4 = (idx & 15) * 4;                               \
            cpa16(vsB + (r * APAD + c4) * 4,                                     \
                  Vb + (size_t)((kt) * 128 + r) * DD + c4);                      \
        }                                                                        \
        cp_commit();                                                             \
    } while (0)

    // Stage Q tile (tf32, pre-scaled by 0.125 upstream) and hoist fragments.
#pragma unroll
    for (int i = 0; i < 8; i++) {
        int idx = tid + i * 256;
        int r = idx >> 4, c = (idx & 15) * 4;
        uint4 v = *(const uint4*)(Qb + (size_t)(q0 + r) * DD + c);
        uint32_t* p = Qs + r * APAD + c;
        p[0] = v.x; p[1] = v.y; p[2] = v.z; p[3] = v.w;
    }
    __syncthreads();

    uint32_t qf[8][4][4];   // [ks][mi][frag] — Q resident
#pragma unroll
    for (int ks = 0; ks < 8; ks++)
#pragma unroll
        for (int mi = 0; mi < 4; mi++)
            ldsm4(qf[ks][mi], qA + (mi * 16 * APAD + ks * 8) * 4);

    // ---------------- Pass 1: row sums of exp(S) ----------------
    float rs[8] = {};
    KSTAGE(0, 0);
    for (int kt = 0; kt < 16; kt++) {
        if (kt < 15) { KSTAGE((kt + 1) & 1, kt + 1); cp_wait1(); }
        else         { cp_wait0(); }
        __syncthreads();
        uint32_t kbase = ksB + (kt & 1) * 128 * APAD * 4 + kB;
#pragma unroll
        for (int half = 0; half < 2; half++) {
            float acc[4][2][4] = {};
#pragma unroll
            for (int ks = 0; ks < 8; ks++) {
                uint32_t bf[2][2];
#pragma unroll
                for (int ni = 0; ni < 2; ni++)
                    ldsm2(bf[ni], kbase + ((half * 2 + ni) * 8 * APAD + ks * 8) * 4);
#pragma unroll
                for (int mi = 0; mi < 4; mi++)
#pragma unroll
                    for (int ni = 0; ni < 2; ni++)
                        mma8(acc[mi][ni], qf[ks][mi], bf[ni]);
            }
#pragma unroll
            for (int mi = 0; mi < 4; mi++)
#pragma unroll
                for (int ni = 0; ni < 2; ni++) {
                    rs[mi * 2 + 0] += __expf(acc[mi][ni][0]) + __expf(acc[mi][ni][1]);
                    rs[mi * 2 + 1] += __expf(acc[mi][ni][2]) + __expf(acc[mi][ni][3]);
                }
        }
        __syncthreads();
    }
    // Deterministic cross-warp row-sum reduction.
#pragma unroll
    for (int j = 0; j < 8; j++) {
        float v = rs[j];
        v += __shfl_xor_sync(0xffffffffu, v, 1);
        v += __shfl_xor_sync(0xffffffffu, v, 2);
        if (tig == 0)
            part[wn * 128 + wm * 64 + (j >> 1) * 16 + g + (j & 1) * 8] = v;
    }
    __syncthreads();
    if (tid < 128)
        rinv[tid] = 1.0f / (part[tid] + part[128 + tid] + part[256 + tid] + part[384 + tid]);
    __syncthreads();

    // ---------------- Pass 2: P out + P*V ----------------
    float acc_o[2][4][4] = {};
    KSTAGE(0, 0);
    for (int kt = 0; kt < 16; kt++) {
        if (kt < 15) KSTAGE((kt + 1) & 1, kt + 1);
        VSTAGE(kt);
        if (kt < 15) cp_wait2(); else cp_wait1();   // K(kt) ready
        __syncthreads();
        uint32_t kbase = ksB + (kt & 1) * 128 * APAD * 4 + kB;
#pragma unroll
        for (int half = 0; half < 2; half++) {
            float acc[4][2][4] = {};
#pragma unroll
            for (int ks = 0; ks < 8; ks++) {
                uint32_t bf[2][2];
#pragma unroll
                for (int ni = 0; ni < 2; ni++)
                    ldsm2(bf[ni], kbase + ((half * 2 + ni) * 8 * APAD + ks * 8) * 4);
#pragma unroll
                for (int mi = 0; mi < 4; mi++)
#pragma unroll
                    for (int ni = 0; ni < 2; ni++)
                        mma8(acc[mi][ni], qf[ks][mi], bf[ni]);
            }
            // Normalize, emit P to gmem (streaming) and smem (tf32).
#pragma unroll
            for (int mi = 0; mi < 4; mi++) {
                int rl = wm * 64 + mi * 16 + g;
                float ri0 = rinv[rl], ri1 = rinv[rl + 8];
#pragma unroll
                for (int ni = 0; ni < 2; ni++) {
                    int cl = wn * 32 + (half * 2 + ni) * 8 + tig * 2;
                    float p0 = __expf(acc[mi][ni][0]) * ri0;
                    float p1 = __expf(acc[mi][ni][1]) * ri0;
                    float p2 = __expf(acc[mi][ni][2]) * ri1;
                    float p3 = __expf(acc[mi][ni][3]) * ri1;
                    stcs2(outP + (size_t)(q0 + rl) * NK + kt * 128 + cl, p0, p1);
                    stcs2(outP + (size_t)(q0 + rl + 8) * NK + kt * 128 + cl, p2, p3);
                    uint32_t* pp = Ps + rl * PPAD + cl;
                    pp[0] = f2tf(p0); pp[1] = f2tf(p1);
                    uint32_t* pq = Ps + (rl + 8) * PPAD + cl;
                    pq[0] = f2tf(p2); pq[1] = f2tf(p3);
                }
            }
        }
        if (kt < 15) cp_wait1(); else cp_wait0();   // V(kt) ready
        __syncthreads();                            // Ps + Vs visible
        // O += P(128x128) * V(128x64): 4x2 warp grid, 32x32 tiles
#pragma unroll
        for (int ks = 0; ks < 16; ks++) {
            int k0 = ks * 8;
            uint32_t a[2][4], bf[4][2];
#pragma unroll
            for (int mi = 0; mi < 2; mi++)
                ldsm4(a[mi], pA + (mi * 16 * PPAD + k0) * 4);
#pragma unroll
            for (int ni = 0; ni < 4; ni++) {
                int nb = wn2 * 32 + ni * 8 + g;
                bf[ni][0] = Vs[(k0 + tig) * APAD + nb];
                bf[ni][1] = Vs[(k0 + tig + 4) * APAD + nb];
            }
#pragma unroll
            for (int mi = 0; mi < 2; mi++)
#pragma unroll
                for (int ni = 0; ni < 4; ni++)
                    mma8(acc_o[mi][ni], a[mi], bf[ni]);
        }
        __syncthreads();
    }
#undef KSTAGE
#undef VSTAGE

    // Write O as tf32 bits (consumed by the tf32 out-projection GEMM).
#pragma unroll
    for (int mi = 0; mi < 2; mi++) {
        int r = q0 + wm2 * 32 + mi * 16 + g;
#pragma unroll
        for (int ni = 0; ni < 4; ni++) {
            int c = wn2 * 32 + ni * 8 + tig * 2;
            uint32_t* o0 = O + ((size_t)b * NQ + r) * DD + h * HDIM + c;
            *(uint2*)o0 = make_uint2(f2tf(acc_o[mi][ni][0]), f2tf(acc_o[mi][ni][1]));
            uint32_t* o1 = O + ((size_t)b * NQ + r + 8) * DD + h * HDIM + c;
            *(uint2*)o1 = make_uint2(f2tf(acc_o[mi][ni][2]), f2tf(acc_o[mi][ni][3]));
        }
    }
}

// ---------------------------------------------------------------------------
extern "C" void kernel_launch(void* const* d_in, const int* in_sizes, int n_in,
                              void* d_out, int out_size) {
    const float* q_seq   = (const float*)d_in[0];
    const float* kv_seq  = (const float*)d_in[1];
    const float* Wq      = (const float*)d_in[2];
    const float* bq      = (const float*)d_in[3];
    const float* Wk      = (const float*)d_in[4];
    const float* bk      = (const float*)d_in[5];
    const float* Wv      = (const float*)d_in[6];
    const float* bv      = (const float*)d_in[7];
    const float* Wo      = (const float*)d_in[8];
    const float* bo      = (const float*)d_in[9];
    const float* freqs_q = (const float*)d_in[10];
    const float* freqs_kv= (const float*)d_in[11];

    float* out  = (float*)d_out;
    float* attn = out + (size_t)BB * NQ * DD;

    uint32_t *gQ, *gK, *gV, *gO, *gXq, *gXkv, *gWq, *gWk, *gWv, *gWo;
    cudaGetSymbolAddress((void**)&gQ,  g_Q);
    cudaGetSymbolAddress((void**)&gK,  g_K);
    cudaGetSymbolAddress((void**)&gV,  g_V);
    cudaGetSymbolAddress((void**)&gO,  g_O);
    cudaGetSymbolAddress((void**)&gXq, g_Xq);
    cudaGetSymbolAddress((void**)&gXkv,g_Xkv);
    cudaGetSymbolAddress((void**)&gWq, g_Wq);
    cudaGetSymbolAddress((void**)&gWk, g_Wk);
    cudaGetSymbolAddress((void**)&gWv, g_Wv);
    cudaGetSymbolAddress((void**)&gWo, g_Wo);

    static int attr_done = 0;
    if (!attr_done) {
        cudaFuncSetAttribute(gemm_bias_rope_tc,
                             cudaFuncAttributeMaxDynamicSharedMemorySize, GEMM_SMEM);
        cudaFuncSetAttribute(attn_fused,
                             cudaFuncAttributeMaxDynamicSharedMemorySize, ATTN_SMEM);
        attr_done = 1;
    }

    // Pre-convert fp32 inputs to tf32 once.
    const int SEQ4 = (BB * NQ * DD) / 4;
    const int W4   = (DD * DD) / 4;
    cvt_tf32_kernel<<<(SEQ4 + 255) / 256, 256>>>((const float4*)q_seq,  (uint4*)gXq,  SEQ4);
    cvt_tf32_kernel<<<(SEQ4 + 255) / 256, 256>>>((const float4*)kv_seq, (uint4*)gXkv, SEQ4);
    cvt_tf32_kernel<<<(W4 + 255) / 256, 256>>>((const float4*)Wq, (uint4*)gWq, W4);
    cvt_tf32_kernel<<<(W4 + 255) / 256, 256>>>((const float4*)Wk, (uint4*)gWk, W4);
    cvt_tf32_kernel<<<(W4 + 255) / 256, 256>>>((const float4*)Wv, (uint4*)gWv, W4);
    cvt_tf32_kernel<<<(W4 + 255) / 256, 256>>>((const float4*)Wo, (uint4*)gWo, W4);

    dim3 gproj(DD / GBN, (BB * NQ) / GBM);   // 8 x 16 = 128 blocks

    gemm_bias_rope_tc<<<gproj, 256, GEMM_SMEM>>>(
        gXq, gWq, bq, gQ, BB * NQ, DD, DD, freqs_q, (float)(2 * NQ), 1.0f, 1, 1, 0.125f);
    gemm_bias_rope_tc<<<gproj, 256, GEMM_SMEM>>>(
        gXkv, gWk, bk, gK, BB * NK, DD, DD, freqs_kv, (float)(2 * NK), -1.0f, 1, 1, 1.0f);
    gemm_bias_rope_tc<<<gproj, 256, GEMM_SMEM>>>(
        gXkv, gWv, bv, gV, BB * NK, DD, DD, nullptr, 1.0f, 0.0f, 0, 1, 1.0f);

    attn_fused<<<dim3(NQ / 128, BB * HH), 256, ATTN_SMEM>>>(gQ, gK, gV, attn, gO);

    gemm_bias_rope_tc<<<gproj, 256, GEMM_SMEM>>>(
        gO, gWo, bo, out, BB * NQ, DD, DD, nullptr, 1.0f, 0.0f, 0, 0, 1.0f);
}

// round 12
// speedup vs baseline: 1.0364x; 1.0260x over previous
#include <cuda_runtime.h>
#include <cuda_bf16.h>
#include <math.h>
#include <stdint.h>

#define BB 2
#define NQ 2048
#define NK 2048
#define DD 1024
#define HH 16
#define HDIM 64

// Scratch (allocation-free: __device__ globals)
// Q/K/V/O stored as tf32 bit patterns (uint32_t) — converted at write time.
__device__ uint32_t g_Q[(size_t)BB * NQ * DD];
__device__ uint32_t g_K[(size_t)BB * NK * DD];
__device__ uint32_t g_V[(size_t)BB * NK * DD];
__device__ uint32_t g_O[(size_t)BB * NQ * DD];
// tf32 copies of the fp32 harness inputs
__device__ uint32_t g_Xq[(size_t)BB * NQ * DD];
__device__ uint32_t g_Xkv[(size_t)BB * NK * DD];
__device__ uint32_t g_Wq[(size_t)DD * DD];
__device__ uint32_t g_Wk[(size_t)DD * DD];
__device__ uint32_t g_Wv[(size_t)DD * DD];
__device__ uint32_t g_Wo[(size_t)DD * DD];

// ---------------------------------------------------------------------------
// helpers
// ---------------------------------------------------------------------------
__device__ __forceinline__ uint32_t f2tf(float x) {
    uint32_t y;
    asm("cvt.rna.tf32.f32 %0, %1;" : "=r"(y) : "f"(x));
    return y;
}

__device__ __forceinline__ void mma8(float c[4], const uint32_t a[4], const uint32_t b[2]) {
    asm volatile(
        "mma.sync.aligned.m16n8k8.row.col.f32.tf32.tf32.f32 "
        "{%0,%1,%2,%3}, {%4,%5,%6,%7}, {%8,%9}, {%0,%1,%2,%3};\n"
        : "+f"(c[0]), "+f"(c[1]), "+f"(c[2]), "+f"(c[3])
        : "r"(a[0]), "r"(a[1]), "r"(a[2]), "r"(a[3]), "r"(b[0]), "r"(b[1]));
}

__device__ __forceinline__ void ldsm4(uint32_t a[4], uint32_t addr) {
    asm volatile("ldmatrix.sync.aligned.m8n8.x4.shared.b16 {%0,%1,%2,%3}, [%4];"
                 : "=r"(a[0]), "=r"(a[1]), "=r"(a[2]), "=r"(a[3]) : "r"(addr));
}
__device__ __forceinline__ void ldsm2(uint32_t b[2], uint32_t addr) {
    asm volatile("ldmatrix.sync.aligned.m8n8.x2.shared.b16 {%0,%1}, [%2];"
                 : "=r"(b[0]), "=r"(b[1]) : "r"(addr));
}

__device__ __forceinline__ void cpa16(uint32_t dst_smem, const void* src) {
    asm volatile("cp.async.cg.shared.global [%0], [%1], 16;\n" :: "r"(dst_smem), "l"(src));
}
__device__ __forceinline__ void cp_commit() {
    asm volatile("cp.async.commit_group;\n");
}
__device__ __forceinline__ void cp_wait0() { asm volatile("cp.async.wait_group 0;\n"); }
__device__ __forceinline__ void cp_wait1() { asm volatile("cp.async.wait_group 1;\n"); }

__device__ __forceinline__ void stcs2(float* p, float a, float b) {
    asm volatile("st.global.cs.v2.f32 [%0], {%1,%2};\n" :: "l"(p), "f"(a), "f"(b));
}

__device__ __forceinline__ void barsync(int id, int cnt) {
    asm volatile("bar.sync %0, %1;" :: "r"(id), "r"(cnt) : "memory");
}
__device__ __forceinline__ void bararrive(int id, int cnt) {
    asm volatile("bar.arrive %0, %1;" :: "r"(id), "r"(cnt) : "memory");
}

extern __shared__ char smraw[];

// ---------------------------------------------------------------------------
// fp32 -> tf32 bulk converter
// ---------------------------------------------------------------------------
__global__ void cvt_tf32_kernel(const float4* __restrict__ src, uint4* __restrict__ dst,
                                int n4) {
    int i = blockIdx.x * blockDim.x + threadIdx.x;
    if (i < n4) {
        float4 v = src[i];
        uint4 o;
        o.x = f2tf(v.x); o.y = f2tf(v.y); o.z = f2tf(v.z); o.w = f2tf(v.w);
        dst[i] = o;
    }
}

// ---------------------------------------------------------------------------
// Tensor-core GEMM (tf32 inputs) + optional fused xpos-RoPE. (as R11)
// ---------------------------------------------------------------------------
#define GBM 256
#define GBN 128
#define GBK 32
#define GPAD 36
#define GEMM_SMEM ((2 * GBM * GPAD + 2 * GBN * GPAD) * 4)

__global__ void __launch_bounds__(256, 1)
gemm_bias_rope_tc(const uint32_t* __restrict__ X, const uint32_t* __restrict__ W,
                  const float* __restrict__ bias, void* __restrict__ Yout,
                  int M, int N, int K,
                  const float* __restrict__ freqs, float scale_base, float rsign,
                  int do_rope, int out_tf32, float prescale) {
    uint32_t* Xs = (uint32_t*)smraw;
    uint32_t* Ws = Xs + 2 * GBM * GPAD;

    int tid = threadIdx.x;
    int warp = tid >> 5, lane = tid & 31;
    int g = lane >> 2, tig = lane & 3;
    int wm = warp >> 1, wn = warp & 1;
    int row0 = blockIdx.y * GBM, col0 = blockIdx.x * GBN;

    uint32_t xsB = (uint32_t)__cvta_generic_to_shared(Xs);
    uint32_t wsB = (uint32_t)__cvta_generic_to_shared(Ws);

    uint32_t aOff = ((wm * 64 + (lane & 15)) * GPAD + (lane >> 4) * 4) * 4;
    uint32_t bOff = ((wn * 64 + (lane & 7)) * GPAD + ((lane >> 3) & 1) * 4) * 4;

    float acc[4][8][4] = {};

#define GSTAGE(buf, kt)                                                          \
    do {                                                                         \
        _Pragma("unroll")                                                        \
        for (int i = 0; i < 8; i++) {                                            \
            int idx = tid + i * 256;                                             \
            int r = idx >> 3, c4 = (idx & 7) * 4;                                \
            cpa16(xsB + ((buf) * GBM * GPAD + r * GPAD + c4) * 4,                \
                  X + (size_t)(row0 + r) * K + (kt) + c4);                       \
        }                                                                        \
        _Pragma("unroll")                                                        \
        for (int i = 0; i < 4; i++) {                                            \
            int idx = tid + i * 256;                                             \
            int r = idx >> 3, c4 = (idx & 7) * 4;                                \
            cpa16(wsB + ((buf) * GBN * GPAD + r * GPAD + c4) * 4,                \
                  W + (size_t)(col0 + r) * K + (kt) + c4);                       \
        }                                                                        \
        cp_commit();                                                             \
    } while (0)

    GSTAGE(0, 0);
    int T = K / GBK;
    for (int t = 0; t < T; t++) {
        if (t + 1 < T) { GSTAGE((t + 1) & 1, (t + 1) * GBK); cp_wait1(); }
        else           { cp_wait0(); }
        __syncthreads();
        uint32_t xb = xsB + (t & 1) * GBM * GPAD * 4 + aOff;
        uint32_t wb = wsB + (t & 1) * GBN * GPAD * 4 + bOff;
#pragma unroll
        for (int ks = 0; ks < 4; ks++) {
            int k0 = ks * 8;
            uint32_t a[4][4], bf[8][2];
#pragma unroll
            for (int mi = 0; mi < 4; mi++)
                ldsm4(a[mi], xb + (mi * 16 * GPAD + k0) * 4);
#pragma unroll
            for (int ni = 0; ni < 8; ni++)
                ldsm2(bf[ni], wb + (ni * 8 * GPAD + k0) * 4);
#pragma unroll
            for (int mi = 0; mi < 4; mi++)
#pragma unroll
                for (int ni = 0; ni < 8; ni++)
                    mma8(acc[mi][ni], a[mi], bf[ni]);
        }
        __syncthreads();
    }
#undef GSTAGE

#pragma unroll
    for (int mi = 0; mi < 4; mi++) {
        int r = row0 + wm * 64 + mi * 16 + g;
#pragma unroll
        for (int ni = 0; ni < 8; ni++) {
            int c = col0 + wn * 64 + ni * 8 + tig * 2;
            float v0 = acc[mi][ni][0] + bias[c];
            float v1 = acc[mi][ni][1] + bias[c + 1];
            float v2 = acc[mi][ni][2] + bias[c];
            float v3 = acc[mi][ni][3] + bias[c + 1];
            if (do_rope) {
                int cd = c & (HDIM - 1);
                float f = freqs[cd >> 1];
                float sv = ((float)cd + 0.4f * (float)HDIM) / (1.4f * (float)HDIM);
                {
                    float n0 = (float)(r & (NQ - 1));
                    float sn, cs; sincosf(n0 * f, &sn, &cs);
                    float scale = powf(sv, (n0 - (float)(NQ / 2)) / scale_base * rsign);
                    float o0 = (v0 * cs - v1 * sn) * scale;
                    float o1 = (v1 * cs + v0 * sn) * scale;
                    v0 = o0; v1 = o1;
                }
                {
                    float n1 = (float)((r + 8) & (NQ - 1));
                    float sn, cs; sincosf(n1 * f, &sn, &cs);
                    float scale = powf(sv, (n1 - (float)(NQ / 2)) / scale_base * rsign);
                    float o2 = (v2 * cs - v3 * sn) * scale;
                    float o3 = (v3 * cs + v2 * sn) * scale;
                    v2 = o2; v3 = o3;
                }
            }
            if (out_tf32) {
                uint32_t* Y = (uint32_t*)Yout;
                *(uint2*)(Y + (size_t)r * N + c) =
                    make_uint2(f2tf(v0 * prescale), f2tf(v1 * prescale));
                *(uint2*)(Y + (size_t)(r + 8) * N + c) =
                    make_uint2(f2tf(v2 * prescale), f2tf(v3 * prescale));
            } else {
                float* Y = (float*)Yout;
                *(float2*)(Y + (size_t)r * N + c) = make_float2(v0, v1);
                *(float2*)(Y + (size_t)(r + 8) * N + c) = make_float2(v2, v3);
            }
        }
    }
}

// ---------------------------------------------------------------------------
// Warp-specialized fused attention, 512 threads (16 warps).
// Pass 1: warp groups split kt even/odd (each 2x4 S grid, own K buffers).
// Pass 2: warps 0-7 produce S+exp+P (2x4), warps 8-15 consume P*V (4x2),
//         via named-barrier handshake around a single Ps buffer.
// ---------------------------------------------------------------------------
#define APAD 68
#define PPAD 132
#define OK0_W (128 * APAD)
#define OK1_W (2 * 128 * APAD)
#define OV_W  (3 * 128 * APAD)
#define OP_W  (4 * 128 * APAD)
#define OPART_W (OP_W + 128 * PPAD)
#define ORINV_W (OPART_W + 1024)
#define ATTN_SMEM ((ORINV_W + 128) * 4)

__global__ void __launch_bounds__(512, 1)
attn_fused(const uint32_t* __restrict__ Q, const uint32_t* __restrict__ Kg,
           const uint32_t* __restrict__ Vg, float* __restrict__ attn,
           uint32_t* __restrict__ O) {
    uint32_t* smw = (uint32_t*)smraw;
    uint32_t* Qs = smw;                     // [128][APAD] persistent
    uint32_t* Vs = smw + OV_W;              // [128][APAD]
    uint32_t* Ps = smw + OP_W;              // [128][PPAD]
    float* part = (float*)(smw + OPART_W);  // [8][128]
    float* rinv = (float*)(smw + ORINV_W);  // [128]

    int bh = blockIdx.y;
    int b = bh / HH, h = bh % HH;
    int q0 = blockIdx.x * 128;
    const uint32_t* Qb = Q + (size_t)b * NQ * DD + h * HDIM;
    const uint32_t* Kb = Kg + (size_t)b * NK * DD + h * HDIM;
    const uint32_t* Vb = Vg + (size_t)b * NK * DD + h * HDIM;
    float* outP = attn + (size_t)bh * NQ * NK;

    int tid = threadIdx.x;
    int warp = tid >> 5, lane = tid & 31;
    int g = lane >> 2, tig = lane & 3;
    bool producer = warp < 8;
    int gw = producer ? warp : (warp - 8);
    int gtid = tid & 255;
    int wm = gw >> 2, wn = gw & 3;          // 2x4 (S)
    int wm2 = gw >> 1, wn2 = gw & 1;        // 4x2 (PV, consumers)

    uint32_t smB = (uint32_t)__cvta_generic_to_shared(smw);
    uint32_t ks0B = smB + OK0_W * 4;
    uint32_t ks1B = smB + OK1_W * 4;
    uint32_t vsB  = smB + OV_W * 4;
    uint32_t psB  = smB + OP_W * 4;

    uint32_t qA   = smB + ((wm * 64 + (lane & 15)) * APAD + (lane >> 4) * 4) * 4;
    uint32_t kOff = ((wn * 32 + (lane & 7)) * APAD + ((lane >> 3) & 1) * 4) * 4;
    uint32_t pA   = psB + ((wm2 * 32 + (lane & 15)) * PPAD + (lane >> 4) * 4) * 4;

#define KSTAGE_G(dstB, kt)                                                       \
    do {                                                                         \
        _Pragma("unroll")                                                        \
        for (int i_ = 0; i_ < 8; i_++) {                                         \
            int idx_ = gtid + i_ * 256;                                          \
            int r_ = idx_ >> 4, c4_ = (idx_ & 15) * 4;                           \
            cpa16((dstB) + (r_ * APAD + c4_) * 4,                                \
                  Kb + (size_t)((kt) * 128 + r_) * DD + c4_);                    \
        }                                                                        \
        cp_commit();                                                             \
    } while (0)

#define VSTAGE_G(kt)                                                             \
    do {                                                                         \
        _Pragma("unroll")                                                        \
        for (int i_ = 0; i_ < 8; i_++) {                                         \
            int idx_ = gtid + i_ * 256;                                          \
            int r_ = idx_ >> 4, c4_ = (idx_ & 15) * 4;                           \
            cpa16(vsB + (r_ * APAD + c4_) * 4,                                   \
                  Vb + (size_t)((kt) * 128 + r_) * DD + c4_);                    \
        }                                                                        \
        cp_commit();                                                             \
    } while (0)

    // Stage Q tile (tf32, prescaled by 0.125 upstream), all 512 threads.
#pragma unroll
    for (int i = 0; i < 4; i++) {
        int idx = tid + i * 512;
        int r = idx >> 4, c = (idx & 15) * 4;
        uint4 v = *(const uint4*)(Qb + (size_t)(q0 + r) * DD + c);
        uint32_t* p = Qs + r * APAD + c;
        p[0] = v.x; p[1] = v.y; p[2] = v.z; p[3] = v.w;
    }
    __syncthreads();

    // ---------------- Pass 1: row sums of exp(S); kt split even/odd ----------
    uint32_t kb0 = producer ? ks0B : ks1B;
    uint32_t kb1 = producer ? vsB  : psB;   // borrow V / Ps regions as K bufs
    int ktb = producer ? 0 : 1;
    int gbar = producer ? 1 : 2;

    float rs[8] = {};
    KSTAGE_G(kb0, ktb);
    for (int i = 0; i < 8; i++) {
        if (i < 7) { KSTAGE_G((i & 1) ? kb0 : kb1, ktb + 2 * (i + 1)); cp_wait1(); }
        else       { cp_wait0(); }
        barsync(gbar, 256);
        uint32_t kbase = ((i & 1) ? kb1 : kb0) + kOff;
        float acc[4][4][4] = {};
#pragma unroll
        for (int ks = 0; ks < 8; ks++) {
            uint32_t a[4][4], bf[4][2];
#pragma unroll
            for (int mi = 0; mi < 4; mi++)
                ldsm4(a[mi], qA + (mi * 16 * APAD + ks * 8) * 4);
#pragma unroll
            for (int ni = 0; ni < 4; ni++)
                ldsm2(bf[ni], kbase + (ni * 8 * APAD + ks * 8) * 4);
#pragma unroll
            for (int mi = 0; mi < 4; mi++)
#pragma unroll
                for (int ni = 0; ni < 4; ni++)
                    mma8(acc[mi][ni], a[mi], bf[ni]);
        }
#pragma unroll
        for (int mi = 0; mi < 4; mi++)
#pragma unroll
            for (int ni = 0; ni < 4; ni++) {
                rs[mi * 2 + 0] += __expf(acc[mi][ni][0]) + __expf(acc[mi][ni][1]);
                rs[mi * 2 + 1] += __expf(acc[mi][ni][2]) + __expf(acc[mi][ni][3]);
            }
        barsync(gbar, 256);
    }
    // Deterministic reduction: 8 fixed slots (4 per group).
#pragma unroll
    for (int j = 0; j < 8; j++) {
        float v = rs[j];
        v += __shfl_xor_sync(0xffffffffu, v, 1);
        v += __shfl_xor_sync(0xffffffffu, v, 2);
        int slot = (producer ? 0 : 4) + wn;
        if (tig == 0)
            part[slot * 128 + wm * 64 + (j >> 1) * 16 + g + (j & 1) * 8] = v;
    }
    __syncthreads();
    if (tid < 128) {
        float s = 0.0f;
#pragma unroll
        for (int k = 0; k < 8; k++) s += part[k * 128 + tid];
        rinv[tid] = 1.0f / s;
    }
    __syncthreads();

    // ---------------- Pass 2: warp-specialized S/exp/P (prod) + PV (cons) ----
    if (producer) {
        float riv[8];
#pragma unroll
        for (int j = 0; j < 8; j++)
            riv[j] = rinv[wm * 64 + (j >> 1) * 16 + g + (j & 1) * 8];

        KSTAGE_G(ks0B, 0);
        for (int kt = 0; kt < 16; kt++) {
            if (kt < 15) { KSTAGE_G((kt & 1) ? ks0B : ks1B, kt + 1); cp_wait1(); }
            else         { cp_wait0(); }
            barsync(1, 256);                 // K(kt) visible, prev iter done
            uint32_t kbase = ((kt & 1) ? ks1B : ks0B) + kOff;
            float acc[4][4][4] = {};
#pragma unroll
            for (int ks = 0; ks < 8; ks++) {
                uint32_t a[4][4], bf[4][2];
#pragma unroll
                for (int mi = 0; mi < 4; mi++)
                    ldsm4(a[mi], qA + (mi * 16 * APAD + ks * 8) * 4);
#pragma unroll
                for (int ni = 0; ni < 4; ni++)
                    ldsm2(bf[ni], kbase + (ni * 8 * APAD + ks * 8) * 4);
#pragma unroll
                for (int mi = 0; mi < 4; mi++)
#pragma unroll
                    for (int ni = 0; ni < 4; ni++)
                        mma8(acc[mi][ni], a[mi], bf[ni]);
            }
            barsync(4, 512);                 // Ps free (consumers done kt-1)
#pragma unroll
            for (int mi = 0; mi < 4; mi++) {
                int rl = wm * 64 + mi * 16 + g;
                float ri0 = riv[mi * 2], ri1 = riv[mi * 2 + 1];
#pragma unroll
                for (int ni = 0; ni < 4; ni++) {
                    int cl = wn * 32 + ni * 8 + tig * 2;
                    float p0 = __expf(acc[mi][ni][0]) * ri0;
                    float p1 = __expf(acc[mi][ni][1]) * ri0;
                    float p2 = __expf(acc[mi][ni][2]) * ri1;
                    float p3 = __expf(acc[mi][ni][3]) * ri1;
                    stcs2(outP + (size_t)(q0 + rl) * NK + kt * 128 + cl, p0, p1);
                    stcs2(outP + (size_t)(q0 + rl + 8) * NK + kt * 128 + cl, p2, p3);
                    uint32_t* pp = Ps + rl * PPAD + cl;
                    pp[0] = f2tf(p0); pp[1] = f2tf(p1);
                    uint32_t* pq = Ps + (rl + 8) * PPAD + cl;
                    pq[0] = f2tf(p2); pq[1] = f2tf(p3);
                }
            }
            bararrive(3, 512);               // Ps full
            barsync(1, 256);                 // iter end (K buffer safety)
        }
    } else {
        float acc_o[2][4][4] = {};
        bararrive(4, 512);                   // initial: Ps free
        for (int kt = 0; kt < 16; kt++) {
            VSTAGE_G(kt);                    // V load overlaps bar wait
            barsync(3, 512);                 // Ps(kt) full
            cp_wait0();
            barsync(2, 256);                 // V visible to all consumers
#pragma unroll
            for (int ks = 0; ks < 16; ks++) {
                int k0 = ks * 8;
                uint32_t a[2][4], bf[4][2];
#pragma unroll
                for (int mi = 0; mi < 2; mi++)
                    ldsm4(a[mi], pA + (mi * 16 * PPAD + k0) * 4);
#pragma unroll
                for (int ni = 0; ni < 4; ni++) {
                    int nb = wn2 * 32 + ni * 8 + g;
                    bf[ni][0] = Vs[(k0 + tig) * APAD + nb];
                    bf[ni][1] = Vs[(k0 + tig + 4) * APAD + nb];
                }
#pragma unroll
                for (int mi = 0; mi < 2; mi++)
#pragma unroll
                    for (int ni = 0; ni < 4; ni++)
                        mma8(acc_o[mi][ni], a[mi], bf[ni]);
            }
            bararrive(4, 512);               // Ps free
            barsync(2, 256);                 // all consumers done (V reuse)
        }
        // Write O as tf32 bits.
#pragma unroll
        for (int mi = 0; mi < 2; mi++) {
            int r = q0 + wm2 * 32 + mi * 16 + g;
#pragma unroll
            for (int ni = 0; ni < 4; ni++) {
                int c = wn2 * 32 + ni * 8 + tig * 2;
                uint32_t* o0 = O + ((size_t)b * NQ + r) * DD + h * HDIM + c;
                *(uint2*)o0 = make_uint2(f2tf(acc_o[mi][ni][0]), f2tf(acc_o[mi][ni][1]));
                uint32_t* o1 = O + ((size_t)b * NQ + r + 8) * DD + h * HDIM + c;
                *(uint2*)o1 = make_uint2(f2tf(acc_o[mi][ni][2]), f2tf(acc_o[mi][ni][3]));
            }
        }
    }
#undef KSTAGE_G
#undef VSTAGE_G
}

// ---------------------------------------------------------------------------
extern "C" void kernel_launch(void* const* d_in, const int* in_sizes, int n_in,
                              void* d_out, int out_size) {
    const float* q_seq   = (const float*)d_in[0];
    const float* kv_seq  = (const float*)d_in[1];
    const float* Wq      = (const float*)d_in[2];
    const float* bq      = (const float*)d_in[3];
    const float* Wk      = (const float*)d_in[4];
    const float* bk      = (const float*)d_in[5];
    const float* Wv      = (const float*)d_in[6];
    const float* bv      = (const float*)d_in[7];
    const float* Wo      = (const float*)d_in[8];
    const float* bo      = (const float*)d_in[9];
    const float* freqs_q = (const float*)d_in[10];
    const float* freqs_kv= (const float*)d_in[11];

    float* out  = (float*)d_out;
    float* attn = out + (size_t)BB * NQ * DD;

    uint32_t *gQ, *gK, *gV, *gO, *gXq, *gXkv, *gWq, *gWk, *gWv, *gWo;
    cudaGetSymbolAddress((void**)&gQ,  g_Q);
    cudaGetSymbolAddress((void**)&gK,  g_K);
    cudaGetSymbolAddress((void**)&gV,  g_V);
    cudaGetSymbolAddress((void**)&gO,  g_O);
    cudaGetSymbolAddress((void**)&gXq, g_Xq);
    cudaGetSymbolAddress((void**)&gXkv,g_Xkv);
    cudaGetSymbolAddress((void**)&gWq, g_Wq);
    cudaGetSymbolAddress((void**)&gWk, g_Wk);
    cudaGetSymbolAddress((void**)&gWv, g_Wv);
    cudaGetSymbolAddress((void**)&gWo, g_Wo);

    static int attr_done = 0;
    if (!attr_done) {
        cudaFuncSetAttribute(gemm_bias_rope_tc,
                             cudaFuncAttributeMaxDynamicSharedMemorySize, GEMM_SMEM);
        cudaFuncSetAttribute(attn_fused,
                             cudaFuncAttributeMaxDynamicSharedMemorySize, ATTN_SMEM);
        attr_done = 1;
    }

    // Pre-convert fp32 inputs to tf32 once.
    const int SEQ4 = (BB * NQ * DD) / 4;
    const int W4   = (DD * DD) / 4;
    cvt_tf32_kernel<<<(SEQ4 + 255) / 256, 256>>>((const float4*)q_seq,  (uint4*)gXq,  SEQ4);
    cvt_tf32_kernel<<<(SEQ4 + 255) / 256, 256>>>((const float4*)kv_seq, (uint4*)gXkv, SEQ4);
    cvt_tf32_kernel<<<(W4 + 255) / 256, 256>>>((const float4*)Wq, (uint4*)gWq, W4);
    cvt_tf32_kernel<<<(W4 + 255) / 256, 256>>>((const float4*)Wk, (uint4*)gWk, W4);
    cvt_tf32_kernel<<<(W4 + 255) / 256, 256>>>((const float4*)Wv, (uint4*)gWv, W4);
    cvt_tf32_kernel<<<(W4 + 255) / 256, 256>>>((const float4*)Wo, (uint4*)gWo, W4);

    dim3 gproj(DD / GBN, (BB * NQ) / GBM);   // 8 x 16 = 128 blocks

    gemm_bias_rope_tc<<<gproj, 256, GEMM_SMEM>>>(
        gXq, gWq, bq, gQ, BB * NQ, DD, DD, freqs_q, (float)(2 * NQ), 1.0f, 1, 1, 0.125f);
    gemm_bias_rope_tc<<<gproj, 256, GEMM_SMEM>>>(
        gXkv, gWk, bk, gK, BB * NK, DD, DD, freqs_kv, (float)(2 * NK), -1.0f, 1, 1, 1.0f);
    gemm_bias_rope_tc<<<gproj, 256, GEMM_SMEM>>>(
        gXkv, gWv, bv, gV, BB * NK, DD, DD, nullptr, 1.0f, 0.0f, 0, 1, 1.0f);

    attn_fused<<<dim3(NQ / 128, BB * HH), 512, ATTN_SMEM>>>(gQ, gK, gV, attn, gO);

    gemm_bias_rope_tc<<<gproj, 256, GEMM_SMEM>>>(
        gO, gWo, bo, out, BB * NQ, DD, DD, nullptr, 1.0f, 0.0f, 0, 0, 1.0f);
}

// round 13
// speedup vs baseline: 1.5355x; 1.4816x over previous
#include <cuda_runtime.h>
#include <cuda_fp16.h>
#include <math.h>
#include <stdint.h>

#define BB 2
#define NQ 2048
#define NK 2048
#define DD 1024
#define HH 16
#define HDIM 64

// Scratch (allocation-free: __device__ globals), all fp16 at rest.
__device__ __half g_Q[(size_t)BB * NQ * DD];
__device__ __half g_K[(size_t)BB * NK * DD];
__device__ __half g_V[(size_t)BB * NK * DD];
__device__ __half g_O[(size_t)BB * NQ * DD];
__device__ __half g_Xq[(size_t)BB * NQ * DD];
__device__ __half g_Xkv[(size_t)BB * NK * DD];
__device__ __half g_Wq[(size_t)DD * DD];
__device__ __half g_Wk[(size_t)DD * DD];
__device__ __half g_Wv[(size_t)DD * DD];
__device__ __half g_Wo[(size_t)DD * DD];

// ---------------------------------------------------------------------------
// helpers
// ---------------------------------------------------------------------------
__device__ __forceinline__ uint32_t packh2(float a, float b) {
    __half2 h = __floats2half2_rn(a, b);
    return *(uint32_t*)&h;
}

// D(16x8) += A(16x16) * B(16x8), fp16 in, fp32 acc
__device__ __forceinline__ void mma16(float c[4], const uint32_t a[4], const uint32_t b[2]) {
    asm volatile(
        "mma.sync.aligned.m16n8k16.row.col.f32.f16.f16.f32 "
        "{%0,%1,%2,%3}, {%4,%5,%6,%7}, {%8,%9}, {%0,%1,%2,%3};\n"
        : "+f"(c[0]), "+f"(c[1]), "+f"(c[2]), "+f"(c[3])
        : "r"(a[0]), "r"(a[1]), "r"(a[2]), "r"(a[3]), "r"(b[0]), "r"(b[1]));
}

__device__ __forceinline__ void ldsm4(uint32_t a[4], uint32_t addr) {
    asm volatile("ldmatrix.sync.aligned.m8n8.x4.shared.b16 {%0,%1,%2,%3}, [%4];"
                 : "=r"(a[0]), "=r"(a[1]), "=r"(a[2]), "=r"(a[3]) : "r"(addr));
}
__device__ __forceinline__ void ldsm2(uint32_t b[2], uint32_t addr) {
    asm volatile("ldmatrix.sync.aligned.m8n8.x2.shared.b16 {%0,%1}, [%2];"
                 : "=r"(b[0]), "=r"(b[1]) : "r"(addr));
}
__device__ __forceinline__ void ldsm2t(uint32_t b[2], uint32_t addr) {
    asm volatile("ldmatrix.sync.aligned.m8n8.x2.trans.shared.b16 {%0,%1}, [%2];"
                 : "=r"(b[0]), "=r"(b[1]) : "r"(addr));
}

__device__ __forceinline__ void cpa16(uint32_t dst_smem, const void* src) {
    asm volatile("cp.async.cg.shared.global [%0], [%1], 16;\n" :: "r"(dst_smem), "l"(src));
}
__device__ __forceinline__ void cp_commit() {
    asm volatile("cp.async.commit_group;\n");
}
__device__ __forceinline__ void cp_wait0() { asm volatile("cp.async.wait_group 0;\n"); }
__device__ __forceinline__ void cp_wait1() { asm volatile("cp.async.wait_group 1;\n"); }
__device__ __forceinline__ void cp_wait2() { asm volatile("cp.async.wait_group 2;\n"); }

__device__ __forceinline__ void stcs2(float* p, float a, float b) {
    asm volatile("st.global.cs.v2.f32 [%0], {%1,%2};\n" :: "l"(p), "f"(a), "f"(b));
}

extern __shared__ char smraw[];

// ---------------------------------------------------------------------------
// fp32 -> fp16 bulk converter
// ---------------------------------------------------------------------------
__global__ void cvt_f16_kernel(const float4* __restrict__ src, uint2* __restrict__ dst,
                               int n4) {
    int i = blockIdx.x * blockDim.x + threadIdx.x;
    if (i < n4) {
        float4 v = src[i];
        dst[i] = make_uint2(packh2(v.x, v.y), packh2(v.z, v.w));
    }
}

// ---------------------------------------------------------------------------
// Tensor-core GEMM (fp16 in, fp32 acc) + optional fused xpos-RoPE epilogue.
// 256x128 tile, k-tile 32, cp.async double-buffered, 8 warps 4x2,
// warp tile 64x64, all fragments via ldmatrix, m16n8k16 MMA.
// ---------------------------------------------------------------------------
#define GBM 256
#define GBN 128
#define GBK 32
#define GPADH 40     // halves pitch (80 bytes, 16B-aligned, conflict-free)
#define GEMM_SMEM ((2 * GBM * GPADH + 2 * GBN * GPADH) * 2)

__global__ void __launch_bounds__(256, 1)
gemm_bias_rope_tc(const __half* __restrict__ X, const __half* __restrict__ W,
                  const float* __restrict__ bias, void* __restrict__ Yout,
                  int M, int N, int K,
                  const float* __restrict__ freqs, float scale_base, float rsign,
                  int do_rope, int out_f16, float prescale) {
    int tid = threadIdx.x;
    int warp = tid >> 5, lane = tid & 31;
    int g = lane >> 2, tig = lane & 3;
    int wm = warp >> 1, wn = warp & 1;
    int row0 = blockIdx.y * GBM, col0 = blockIdx.x * GBN;

    uint32_t xsB = (uint32_t)__cvta_generic_to_shared(smraw);
    uint32_t wsB = xsB + 2 * GBM * GPADH * 2;

    uint32_t aOff = ((wm * 64 + (lane & 15)) * GPADH + (lane >> 4) * 8) * 2;
    uint32_t bOff = ((wn * 64 + (lane & 7)) * GPADH + ((lane >> 3) & 1) * 8) * 2;

    float acc[4][8][4] = {};

#define GSTAGE(buf, kt)                                                          \
    do {                                                                         \
        _Pragma("unroll")                                                        \
        for (int i = 0; i < 4; i++) {                                            \
            int idx = tid + i * 256;                                             \
            int r = idx >> 2, c8 = (idx & 3) * 8;                                \
            cpa16(xsB + ((buf) * GBM * GPADH + r * GPADH + c8) * 2,              \
                  X + (size_t)(row0 + r) * K + (kt) + c8);                       \
        }                                                                        \
        _Pragma("unroll")                                                        \
        for (int i = 0; i < 2; i++) {                                            \
            int idx = tid + i * 256;                                             \
            int r = idx >> 2, c8 = (idx & 3) * 8;                                \
            cpa16(wsB + ((buf) * GBN * GPADH + r * GPADH + c8) * 2,              \
                  W + (size_t)(col0 + r) * K + (kt) + c8);                       \
        }                                                                        \
        cp_commit();                                                             \
    } while (0)

    GSTAGE(0, 0);
    int T = K / GBK;
    for (int t = 0; t < T; t++) {
        if (t + 1 < T) { GSTAGE((t + 1) & 1, (t + 1) * GBK); cp_wait1(); }
        else           { cp_wait0(); }
        __syncthreads();
        uint32_t xb = xsB + (t & 1) * GBM * GPADH * 2 + aOff;
        uint32_t wb = wsB + (t & 1) * GBN * GPADH * 2 + bOff;
#pragma unroll
        for (int ks = 0; ks < 2; ks++) {
            int k0 = ks * 16;
            uint32_t a[4][4], bf[8][2];
#pragma unroll
            for (int mi = 0; mi < 4; mi++)
                ldsm4(a[mi], xb + (mi * 16 * GPADH + k0) * 2);
#pragma unroll
            for (int ni = 0; ni < 8; ni++)
                ldsm2(bf[ni], wb + (ni * 8 * GPADH + k0) * 2);
#pragma unroll
            for (int mi = 0; mi < 4; mi++)
#pragma unroll
                for (int ni = 0; ni < 8; ni++)
                    mma16(acc[mi][ni], a[mi], bf[ni]);
        }
        __syncthreads();
    }
#undef GSTAGE

#pragma unroll
    for (int mi = 0; mi < 4; mi++) {
        int r = row0 + wm * 64 + mi * 16 + g;
#pragma unroll
        for (int ni = 0; ni < 8; ni++) {
            int c = col0 + wn * 64 + ni * 8 + tig * 2;
            float v0 = acc[mi][ni][0] + bias[c];
            float v1 = acc[mi][ni][1] + bias[c + 1];
            float v2 = acc[mi][ni][2] + bias[c];
            float v3 = acc[mi][ni][3] + bias[c + 1];
            if (do_rope) {
                int cd = c & (HDIM - 1);
                float f = freqs[cd >> 1];
                float sv = ((float)cd + 0.4f * (float)HDIM) / (1.4f * (float)HDIM);
                {
                    float n0 = (float)(r & (NQ - 1));
                    float sn, cs; sincosf(n0 * f, &sn, &cs);
                    float scale = powf(sv, (n0 - (float)(NQ / 2)) / scale_base * rsign);
                    float o0 = (v0 * cs - v1 * sn) * scale;
                    float o1 = (v1 * cs + v0 * sn) * scale;
                    v0 = o0; v1 = o1;
                }
                {
                    float n1 = (float)((r + 8) & (NQ - 1));
                    float sn, cs; sincosf(n1 * f, &sn, &cs);
                    float scale = powf(sv, (n1 - (float)(NQ / 2)) / scale_base * rsign);
                    float o2 = (v2 * cs - v3 * sn) * scale;
                    float o3 = (v3 * cs + v2 * sn) * scale;
                    v2 = o2; v3 = o3;
                }
            }
            if (out_f16) {
                __half* Y = (__half*)Yout;
                *(uint32_t*)(Y + (size_t)r * N + c) = packh2(v0 * prescale, v1 * prescale);
                *(uint32_t*)(Y + (size_t)(r + 8) * N + c) = packh2(v2 * prescale, v3 * prescale);
            } else {
                float* Y = (float*)Yout;
                *(float2*)(Y + (size_t)r * N + c) = make_float2(v0, v1);
                *(float2*)(Y + (size_t)(r + 8) * N + c) = make_float2(v2, v3);
            }
        }
    }
}

// ---------------------------------------------------------------------------
// Fused attention (fp16 data, fp32 accum), 256 threads, Q fragments resident
// in registers, K/P fragments via ldmatrix, V via ldmatrix.trans.
// Pass 1: rowsums of exp(S); Pass 2: recompute S (bit-identical), write
// P (fp32, streaming) + stage P fp16, accumulate O = P*V.
// ---------------------------------------------------------------------------
#define APADH 72     // halves pitch (144 B, 16B-aligned, conflict-free)
#define PPADH 136
#define OQ_B 0
#define OK_B (128 * APADH * 2)
#define OV_B (OK_B + 2 * 128 * APADH * 2)
#define OP_B (OV_B + 128 * APADH * 2)
#define OPART_B (OP_B + 128 * PPADH * 2)
#define ORINV_B (OPART_B + 512 * 4)
#define ATTN_SMEM (ORINV_B + 128 * 4)

__global__ void __launch_bounds__(256, 1)
attn_fused(const __half* __restrict__ Q, const __half* __restrict__ Kg,
           const __half* __restrict__ Vg, float* __restrict__ attn,
           __half* __restrict__ O) {
    char* smb = smraw;
    __half* Ps = (__half*)(smb + OP_B);
    float* part = (float*)(smb + OPART_B);  // [4][128]
    float* rinv = (float*)(smb + ORINV_B);  // [128]

    int bh = blockIdx.y;
    int b = bh / HH, h = bh % HH;
    int q0 = blockIdx.x * 128;
    const __half* Qb = Q + (size_t)b * NQ * DD + h * HDIM;
    const __half* Kb = Kg + (size_t)b * NK * DD + h * HDIM;
    const __half* Vb = Vg + (size_t)b * NK * DD + h * HDIM;
    float* outP = attn + (size_t)bh * NQ * NK;

    int tid = threadIdx.x;
    int warp = tid >> 5, lane = tid & 31;
    int g = lane >> 2, tig = lane & 3;
    int wm = warp >> 2, wn = warp & 3;      // 2x4 (S): 64x32 warp tiles
    int wm2 = warp >> 1, wn2 = warp & 1;    // 4x2 (PV): 32x32 warp tiles

    uint32_t smB = (uint32_t)__cvta_generic_to_shared(smb);
    uint32_t qsB = smB + OQ_B;
    uint32_t ksB = smB + OK_B;
    uint32_t vsB = smB + OV_B;
    uint32_t psB = smB + OP_B;

    // ldmatrix per-lane bases
    uint32_t qA   = qsB + ((wm * 64 + (lane & 15)) * APADH + (lane >> 4) * 8) * 2;
    uint32_t kOff = ((wn * 32 + (lane & 7)) * APADH + ((lane >> 3) & 1) * 8) * 2;
    uint32_t pA   = psB + ((wm2 * 32 + (lane & 15)) * PPADH + (lane >> 4) * 8) * 2;
    uint32_t vA   = vsB + (((lane & 7) + ((lane >> 3) & 1) * 8) * APADH) * 2;  // trans

#define KSTAGE(buf, kt)                                                          \
    do {                                                                         \
        _Pragma("unroll")                                                        \
        for (int i = 0; i < 4; i++) {                                            \
            int idx = tid + i * 256;                                             \
            int r = idx >> 3, c8 = (idx & 7) * 8;                                \
            cpa16(ksB + ((buf) * 128 * APADH + r * APADH + c8) * 2,              \
                  Kb + (size_t)((kt) * 128 + r) * DD + c8);                      \
        }                                                                        \
        cp_commit();                                                             \
    } while (0)

#define VSTAGE(kt)                                                               \
    do {                                                                         \
        _Pragma("unroll")                                                        \
        for (int i = 0; i < 4; i++) {                                            \
            int idx = tid + i * 256;                                             \
            int r = idx >> 3, c8 = (idx & 7) * 8;                                \
            cpa16(vsB + (r * APADH + c8) * 2,                                    \
                  Vb + (size_t)((kt) * 128 + r) * DD + c8);                      \
        }                                                                        \
        cp_commit();                                                             \
    } while (0)

    // Stage Q tile (fp16, prescaled by 0.125 upstream), hoist fragments.
#pragma unroll
    for (int i = 0; i < 4; i++) {
        int idx = tid + i * 256;
        int r = idx >> 3, c8 = (idx & 7) * 8;
        cpa16(qsB + (r * APADH + c8) * 2, Qb + (size_t)(q0 + r) * DD + c8);
    }
    cp_commit();
    cp_wait0();
    __syncthreads();

    uint32_t qf[4][4][4];   // [ks][mi][frag] — Q resident, 64 regs
#pragma unroll
    for (int ks = 0; ks < 4; ks++)
#pragma unroll
        for (int mi = 0; mi < 4; mi++)
            ldsm4(qf[ks][mi], qA + (mi * 16 * APADH + ks * 16) * 2);

    // ---------------- Pass 1: row sums of exp(S) ----------------
    float rs[8] = {};
    KSTAGE(0, 0);
    for (int kt = 0; kt < 16; kt++) {
        if (kt < 15) { KSTAGE((kt + 1) & 1, kt + 1); cp_wait1(); }
        else         { cp_wait0(); }
        __syncthreads();
        uint32_t kbase = ksB + (kt & 1) * 128 * APADH * 2 + kOff;
        float acc[4][4][4] = {};
#pragma unroll
        for (int ks = 0; ks < 4; ks++) {
            uint32_t bf[4][2];
#pragma unroll
            for (int ni = 0; ni < 4; ni++)
                ldsm2(bf[ni], kbase + (ni * 8 * APADH + ks * 16) * 2);
#pragma unroll
            for (int mi = 0; mi < 4; mi++)
#pragma unroll
                for (int ni = 0; ni < 4; ni++)
                    mma16(acc[mi][ni], qf[ks][mi], bf[ni]);
        }
#pragma unroll
        for (int mi = 0; mi < 4; mi++)
#pragma unroll
            for (int ni = 0; ni < 4; ni++) {
                rs[mi * 2 + 0] += __expf(acc[mi][ni][0]) + __expf(acc[mi][ni][1]);
                rs[mi * 2 + 1] += __expf(acc[mi][ni][2]) + __expf(acc[mi][ni][3]);
            }
        __syncthreads();
    }
    // Deterministic cross-warp row-sum reduction.
#pragma unroll
    for (int j = 0; j < 8; j++) {
        float v = rs[j];
        v += __shfl_xor_sync(0xffffffffu, v, 1);
        v += __shfl_xor_sync(0xffffffffu, v, 2);
        if (tig == 0)
            part[wn * 128 + wm * 64 + (j >> 1) * 16 + g + (j & 1) * 8] = v;
    }
    __syncthreads();
    if (tid < 128)
        rinv[tid] = 1.0f / (part[tid] + part[128 + tid] + part[256 + tid] + part[384 + tid]);
    __syncthreads();

    // ---------------- Pass 2: P out + P*V ----------------
    float acc_o[2][4][4] = {};
    KSTAGE(0, 0);
    for (int kt = 0; kt < 16; kt++) {
        if (kt < 15) KSTAGE((kt + 1) & 1, kt + 1);
        VSTAGE(kt);
        if (kt < 15) cp_wait2(); else cp_wait1();   // K(kt) ready
        __syncthreads();
        uint32_t kbase = ksB + (kt & 1) * 128 * APADH * 2 + kOff;
        float acc[4][4][4] = {};
#pragma unroll
        for (int ks = 0; ks < 4; ks++) {
            uint32_t bf[4][2];
#pragma unroll
            for (int ni = 0; ni < 4; ni++)
                ldsm2(bf[ni], kbase + (ni * 8 * APADH + ks * 16) * 2);
#pragma unroll
            for (int mi = 0; mi < 4; mi++)
#pragma unroll
                for (int ni = 0; ni < 4; ni++)
                    mma16(acc[mi][ni], qf[ks][mi], bf[ni]);
        }
        // Normalize, emit P to gmem (fp32, streaming) and smem (fp16).
#pragma unroll
        for (int mi = 0; mi < 4; mi++) {
            int rl = wm * 64 + mi * 16 + g;
            float ri0 = rinv[rl], ri1 = rinv[rl + 8];
#pragma unroll
            for (int ni = 0; ni < 4; ni++) {
                int cl = wn * 32 + ni * 8 + tig * 2;
                float p0 = __expf(acc[mi][ni][0]) * ri0;
                float p1 = __expf(acc[mi][ni][1]) * ri0;
                float p2 = __expf(acc[mi][ni][2]) * ri1;
                float p3 = __expf(acc[mi][ni][3]) * ri1;
                stcs2(outP + (size_t)(q0 + rl) * NK + kt * 128 + cl, p0, p1);
                stcs2(outP + (size_t)(q0 + rl + 8) * NK + kt * 128 + cl, p2, p3);
                *(uint32_t*)(Ps + rl * PPADH + cl) = packh2(p0, p1);
                *(uint32_t*)(Ps + (rl + 8) * PPADH + cl) = packh2(p2, p3);
            }
        }
        if (kt < 15) cp_wait1(); else cp_wait0();   // V(kt) ready
        __syncthreads();                            // Ps + Vs visible
        // O += P(128x128) * V(128x64): 4x2 warp grid, 32x32 tiles
#pragma unroll
        for (int ks = 0; ks < 8; ks++) {
            int k0 = ks * 16;
            uint32_t a[2][4], bf[4][2];
#pragma unroll
            for (int mi = 0; mi < 2; mi++)
                ldsm4(a[mi], pA + (mi * 16 * PPADH + k0) * 2);
#pragma unroll
            for (int ni = 0; ni < 4; ni++) {
                int nb = wn2 * 32 + ni * 8;
                ldsm2t(bf[ni], vA + (k0 * APADH + nb) * 2);
            }
#pragma unroll
            for (int mi = 0; mi < 2; mi++)
#pragma unroll
                for (int ni = 0; ni < 4; ni++)
                    mma16(acc_o[mi][ni], a[mi], bf[ni]);
        }
        __syncthreads();
    }
#undef KSTAGE
#undef VSTAGE

    // Write O as fp16 (consumed by the fp16 out-projection GEMM).
#pragma unroll
    for (int mi = 0; mi < 2; mi++) {
        int r = q0 + wm2 * 32 + mi * 16 + g;
#pragma unroll
        for (int ni = 0; ni < 4; ni++) {
            int c = wn2 * 32 + ni * 8 + tig * 2;
            __half* o0 = O + ((size_t)b * NQ + r) * DD + h * HDIM + c;
            *(uint32_t*)o0 = packh2(acc_o[mi][ni][0], acc_o[mi][ni][1]);
            __half* o1 = O + ((size_t)b * NQ + r + 8) * DD + h * HDIM + c;
            *(uint32_t*)o1 = packh2(acc_o[mi][ni][2], acc_o[mi][ni][3]);
        }
    }
}

// ---------------------------------------------------------------------------
extern "C" void kernel_launch(void* const* d_in, const int* in_sizes, int n_in,
                              void* d_out, int out_size) {
    const float* q_seq   = (const float*)d_in[0];
    const float* kv_seq  = (const float*)d_in[1];
    const float* Wq      = (const float*)d_in[2];
    const float* bq      = (const float*)d_in[3];
    const float* Wk      = (const float*)d_in[4];
    const float* bk      = (const float*)d_in[5];
    const float* Wv      = (const float*)d_in[6];
    const float* bv      = (const float*)d_in[7];
    const float* Wo      = (const float*)d_in[8];
    const float* bo      = (const float*)d_in[9];
    const float* freqs_q = (const float*)d_in[10];
    const float* freqs_kv= (const float*)d_in[11];

    float* out  = (float*)d_out;
    float* attn = out + (size_t)BB * NQ * DD;

    __half *gQ, *gK, *gV, *gO, *gXq, *gXkv, *gWq, *gWk, *gWv, *gWo;
    cudaGetSymbolAddress((void**)&gQ,  g_Q);
    cudaGetSymbolAddress((void**)&gK,  g_K);
    cudaGetSymbolAddress((void**)&gV,  g_V);
    cudaGetSymbolAddress((void**)&gO,  g_O);
    cudaGetSymbolAddress((void**)&gXq, g_Xq);
    cudaGetSymbolAddress((void**)&gXkv,g_Xkv);
    cudaGetSymbolAddress((void**)&gWq, g_Wq);
    cudaGetSymbolAddress((void**)&gWk, g_Wk);
    cudaGetSymbolAddress((void**)&gWv, g_Wv);
    cudaGetSymbolAddress((void**)&gWo, g_Wo);

    static int attr_done = 0;
    if (!attr_done) {
        cudaFuncSetAttribute(gemm_bias_rope_tc,
                             cudaFuncAttributeMaxDynamicSharedMemorySize, GEMM_SMEM);
        cudaFuncSetAttribute(attn_fused,
                             cudaFuncAttributeMaxDynamicSharedMemorySize, ATTN_SMEM);
        attr_done = 1;
    }

    // Pre-convert fp32 inputs to fp16 once (~15 us of bandwidth kernels).
    const int SEQ4 = (BB * NQ * DD) / 4;
    const int W4   = (DD * DD) / 4;
    cvt_f16_kernel<<<(SEQ4 + 255) / 256, 256>>>((const float4*)q_seq,  (uint2*)gXq,  SEQ4);
    cvt_f16_kernel<<<(SEQ4 + 255) / 256, 256>>>((const float4*)kv_seq, (uint2*)gXkv, SEQ4);
    cvt_f16_kernel<<<(W4 + 255) / 256, 256>>>((const float4*)Wq, (uint2*)gWq, W4);
    cvt_f16_kernel<<<(W4 + 255) / 256, 256>>>((const float4*)Wk, (uint2*)gWk, W4);
    cvt_f16_kernel<<<(W4 + 255) / 256, 256>>>((const float4*)Wv, (uint2*)gWv, W4);
    cvt_f16_kernel<<<(W4 + 255) / 256, 256>>>((const float4*)Wo, (uint2*)gWo, W4);

    dim3 gproj(DD / GBN, (BB * NQ) / GBM);   // 8 x 16 = 128 blocks

    // Q: rope(+1), fp16 out pre-scaled by 0.125 (exact pow2).
    gemm_bias_rope_tc<<<gproj, 256, GEMM_SMEM>>>(
        gXq, gWq, bq, gQ, BB * NQ, DD, DD, freqs_q, (float)(2 * NQ), 1.0f, 1, 1, 0.125f);
    // K: rope(-1), fp16 out.
    gemm_bias_rope_tc<<<gproj, 256, GEMM_SMEM>>>(
        gXkv, gWk, bk, gK, BB * NK, DD, DD, freqs_kv, (float)(2 * NK), -1.0f, 1, 1, 1.0f);
    // V: no rope, fp16 out.
    gemm_bias_rope_tc<<<gproj, 256, GEMM_SMEM>>>(
        gXkv, gWv, bv, gV, BB * NK, DD, DD, nullptr, 1.0f, 0.0f, 0, 1, 1.0f);

    attn_fused<<<dim3(NQ / 128, BB * HH), 256, ATTN_SMEM>>>(gQ, gK, gV, attn, gO);

    // Out-projection: fp32 output.
    gemm_bias_rope_tc<<<gproj, 256, GEMM_SMEM>>>(
        gO, gWo, bo, out, BB * NQ, DD, DD, nullptr, 1.0f, 0.0f, 0, 0, 1.0f);
}

// round 14
// speedup vs baseline: 1.6572x; 1.0793x over previous
#include <cuda_runtime.h>
#include <cuda_fp16.h>
#include <math.h>
#include <stdint.h>

#define BB 2
#define NQ 2048
#define NK 2048
#define DD 1024
#define HH 16
#define HDIM 64

// Scratch (allocation-free: __device__ globals), all fp16 at rest.
__device__ __half g_Q[(size_t)BB * NQ * DD];
__device__ __half g_K[(size_t)BB * NK * DD];
__device__ __half g_V[(size_t)BB * NK * DD];
__device__ __half g_O[(size_t)BB * NQ * DD];
__device__ __half g_Xq[(size_t)BB * NQ * DD];
__device__ __half g_Xkv[(size_t)BB * NK * DD];
__device__ __half g_Wq[(size_t)DD * DD];
__device__ __half g_Wk[(size_t)DD * DD];
__device__ __half g_Wv[(size_t)DD * DD];
__device__ __half g_Wo[(size_t)DD * DD];

// ---------------------------------------------------------------------------
// helpers
// ---------------------------------------------------------------------------
__device__ __forceinline__ uint32_t packh2(float a, float b) {
    __half2 h = __floats2half2_rn(a, b);
    return *(uint32_t*)&h;
}

__device__ __forceinline__ void mma16(float c[4], const uint32_t a[4], const uint32_t b[2]) {
    asm volatile(
        "mma.sync.aligned.m16n8k16.row.col.f32.f16.f16.f32 "
        "{%0,%1,%2,%3}, {%4,%5,%6,%7}, {%8,%9}, {%0,%1,%2,%3};\n"
        : "+f"(c[0]), "+f"(c[1]), "+f"(c[2]), "+f"(c[3])
        : "r"(a[0]), "r"(a[1]), "r"(a[2]), "r"(a[3]), "r"(b[0]), "r"(b[1]));
}

__device__ __forceinline__ void ldsm4(uint32_t a[4], uint32_t addr) {
    asm volatile("ldmatrix.sync.aligned.m8n8.x4.shared.b16 {%0,%1,%2,%3}, [%4];"
                 : "=r"(a[0]), "=r"(a[1]), "=r"(a[2]), "=r"(a[3]) : "r"(addr));
}
__device__ __forceinline__ void ldsm2(uint32_t b[2], uint32_t addr) {
    asm volatile("ldmatrix.sync.aligned.m8n8.x2.shared.b16 {%0,%1}, [%2];"
                 : "=r"(b[0]), "=r"(b[1]) : "r"(addr));
}
__device__ __forceinline__ void ldsm2t(uint32_t b[2], uint32_t addr) {
    asm volatile("ldmatrix.sync.aligned.m8n8.x2.trans.shared.b16 {%0,%1}, [%2];"
                 : "=r"(b[0]), "=r"(b[1]) : "r"(addr));
}

__device__ __forceinline__ void cpa16(uint32_t dst_smem, const void* src) {
    asm volatile("cp.async.cg.shared.global [%0], [%1], 16;\n" :: "r"(dst_smem), "l"(src));
}
__device__ __forceinline__ void cp_commit() {
    asm volatile("cp.async.commit_group;\n");
}
__device__ __forceinline__ void cp_wait0() { asm volatile("cp.async.wait_group 0;\n"); }
__device__ __forceinline__ void cp_wait1() { asm volatile("cp.async.wait_group 1;\n"); }
__device__ __forceinline__ void cp_wait2() { asm volatile("cp.async.wait_group 2;\n"); }

__device__ __forceinline__ void stcs2(float* p, float a, float b) {
    asm volatile("st.global.cs.v2.f32 [%0], {%1,%2};\n" :: "l"(p), "f"(a), "f"(b));
}

extern __shared__ char smraw[];

// ---------------------------------------------------------------------------
// fp32 -> fp16 bulk converter
// ---------------------------------------------------------------------------
__global__ void cvt_f16_kernel(const float4* __restrict__ src, uint2* __restrict__ dst,
                               int n4) {
    int i = blockIdx.x * blockDim.x + threadIdx.x;
    if (i < n4) {
        float4 v = src[i];
        dst[i] = make_uint2(packh2(v.x, v.y), packh2(v.z, v.w));
    }
}

// ---------------------------------------------------------------------------
// Tensor-core GEMM (fp16 in, fp32 acc) + optional fused xpos-RoPE epilogue.
// (unchanged from R13)
// ---------------------------------------------------------------------------
#define GBM 256
#define GBN 128
#define GBK 32
#define GPADH 40
#define GEMM_SMEM ((2 * GBM * GPADH + 2 * GBN * GPADH) * 2)

__global__ void __launch_bounds__(256, 1)
gemm_bias_rope_tc(const __half* __restrict__ X, const __half* __restrict__ W,
                  const float* __restrict__ bias, void* __restrict__ Yout,
                  int M, int N, int K,
                  const float* __restrict__ freqs, float scale_base, float rsign,
                  int do_rope, int out_f16, float prescale) {
    int tid = threadIdx.x;
    int warp = tid >> 5, lane = tid & 31;
    int g = lane >> 2, tig = lane & 3;
    int wm = warp >> 1, wn = warp & 1;
    int row0 = blockIdx.y * GBM, col0 = blockIdx.x * GBN;

    uint32_t xsB = (uint32_t)__cvta_generic_to_shared(smraw);
    uint32_t wsB = xsB + 2 * GBM * GPADH * 2;

    uint32_t aOff = ((wm * 64 + (lane & 15)) * GPADH + (lane >> 4) * 8) * 2;
    uint32_t bOff = ((wn * 64 + (lane & 7)) * GPADH + ((lane >> 3) & 1) * 8) * 2;

    float acc[4][8][4] = {};

#define GSTAGE(buf, kt)                                                          \
    do {                                                                         \
        _Pragma("unroll")                                                        \
        for (int i = 0; i < 4; i++) {                                            \
            int idx = tid + i * 256;                                             \
            int r = idx >> 2, c8 = (idx & 3) * 8;                                \
            cpa16(xsB + ((buf) * GBM * GPADH + r * GPADH + c8) * 2,              \
                  X + (size_t)(row0 + r) * K + (kt) + c8);                       \
        }                                                                        \
        _Pragma("unroll")                                                        \
        for (int i = 0; i < 2; i++) {                                            \
            int idx = tid + i * 256;                                             \
            int r = idx >> 2, c8 = (idx & 3) * 8;                                \
            cpa16(wsB + ((buf) * GBN * GPADH + r * GPADH + c8) * 2,              \
                  W + (size_t)(col0 + r) * K + (kt) + c8);                       \
        }                                                                        \
        cp_commit();                                                             \
    } while (0)

    GSTAGE(0, 0);
    int T = K / GBK;
    for (int t = 0; t < T; t++) {
        if (t + 1 < T) { GSTAGE((t + 1) & 1, (t + 1) * GBK); cp_wait1(); }
        else           { cp_wait0(); }
        __syncthreads();
        uint32_t xb = xsB + (t & 1) * GBM * GPADH * 2 + aOff;
        uint32_t wb = wsB + (t & 1) * GBN * GPADH * 2 + bOff;
#pragma unroll
        for (int ks = 0; ks < 2; ks++) {
            int k0 = ks * 16;
            uint32_t a[4][4], bf[8][2];
#pragma unroll
            for (int mi = 0; mi < 4; mi++)
                ldsm4(a[mi], xb + (mi * 16 * GPADH + k0) * 2);
#pragma unroll
            for (int ni = 0; ni < 8; ni++)
                ldsm2(bf[ni], wb + (ni * 8 * GPADH + k0) * 2);
#pragma unroll
            for (int mi = 0; mi < 4; mi++)
#pragma unroll
                for (int ni = 0; ni < 8; ni++)
                    mma16(acc[mi][ni], a[mi], bf[ni]);
        }
        __syncthreads();
    }
#undef GSTAGE

#pragma unroll
    for (int mi = 0; mi < 4; mi++) {
        int r = row0 + wm * 64 + mi * 16 + g;
#pragma unroll
        for (int ni = 0; ni < 8; ni++) {
            int c = col0 + wn * 64 + ni * 8 + tig * 2;
            float v0 = acc[mi][ni][0] + bias[c];
            float v1 = acc[mi][ni][1] + bias[c + 1];
            float v2 = acc[mi][ni][2] + bias[c];
            float v3 = acc[mi][ni][3] + bias[c + 1];
            if (do_rope) {
                int cd = c & (HDIM - 1);
                float f = freqs[cd >> 1];
                float sv = ((float)cd + 0.4f * (float)HDIM) / (1.4f * (float)HDIM);
                {
                    float n0 = (float)(r & (NQ - 1));
                    float sn, cs; sincosf(n0 * f, &sn, &cs);
                    float scale = powf(sv, (n0 - (float)(NQ / 2)) / scale_base * rsign);
                    float o0 = (v0 * cs - v1 * sn) * scale;
                    float o1 = (v1 * cs + v0 * sn) * scale;
                    v0 = o0; v1 = o1;
                }
                {
                    float n1 = (float)((r + 8) & (NQ - 1));
                    float sn, cs; sincosf(n1 * f, &sn, &cs);
                    float scale = powf(sv, (n1 - (float)(NQ / 2)) / scale_base * rsign);
                    float o2 = (v2 * cs - v3 * sn) * scale;
                    float o3 = (v3 * cs + v2 * sn) * scale;
                    v2 = o2; v3 = o3;
                }
            }
            if (out_f16) {
                __half* Y = (__half*)Yout;
                *(uint32_t*)(Y + (size_t)r * N + c) = packh2(v0 * prescale, v1 * prescale);
                *(uint32_t*)(Y + (size_t)(r + 8) * N + c) = packh2(v2 * prescale, v3 * prescale);
            } else {
                float* Y = (float*)Yout;
                *(float2*)(Y + (size_t)r * N + c) = make_float2(v0, v1);
                *(float2*)(Y + (size_t)(r + 8) * N + c) = make_float2(v2, v3);
            }
        }
    }
}

// ---------------------------------------------------------------------------
// Fused attention, 64-row q-tiles, 2 CTAs/SM (inter-CTA phase overlap).
// 256 threads. S: 2x4 warp grid (32x32 tiles); PV: 4x2 (16x32 tiles).
// Q fragments register-resident; K/P via ldmatrix; V via ldmatrix.trans.
// ---------------------------------------------------------------------------
#define QROWS 64
#define APADH 72
#define PPADH 136
#define OQ_B 0
#define OK_B (QROWS * APADH * 2)                 // 9216
#define OV_B (OK_B + 2 * 128 * APADH * 2)        // 46080
#define OP_B (OV_B + 128 * APADH * 2)            // 64512
#define OPART_B (OP_B + QROWS * PPADH * 2)       // 81920
#define ORINV_B (OPART_B + 4 * QROWS * 4)        // 82944
#define ATTN_SMEM (ORINV_B + QROWS * 4)          // 83200 (x2 = 166 KB/SM)

__global__ void __launch_bounds__(256, 2)
attn_fused(const __half* __restrict__ Q, const __half* __restrict__ Kg,
           const __half* __restrict__ Vg, float* __restrict__ attn,
           __half* __restrict__ O) {
    char* smb = smraw;
    __half* Ps = (__half*)(smb + OP_B);
    float* part = (float*)(smb + OPART_B);  // [4][64]
    float* rinv = (float*)(smb + ORINV_B);  // [64]

    int bh = blockIdx.y;
    int b = bh / HH, h = bh % HH;
    int q0 = blockIdx.x * QROWS;
    const __half* Qb = Q + (size_t)b * NQ * DD + h * HDIM;
    const __half* Kb = Kg + (size_t)b * NK * DD + h * HDIM;
    const __half* Vb = Vg + (size_t)b * NK * DD + h * HDIM;
    float* outP = attn + (size_t)bh * NQ * NK;

    int tid = threadIdx.x;
    int warp = tid >> 5, lane = tid & 31;
    int g = lane >> 2, tig = lane & 3;
    int wm = warp >> 2, wn = warp & 3;      // 2x4 (S): 32x32 warp tiles
    int wm2 = warp >> 1, wn2 = warp & 1;    // 4x2 (PV): 16x32 warp tiles

    uint32_t smB = (uint32_t)__cvta_generic_to_shared(smb);
    uint32_t qsB = smB + OQ_B;
    uint32_t ksB = smB + OK_B;
    uint32_t vsB = smB + OV_B;
    uint32_t psB = smB + OP_B;

    uint32_t qA   = qsB + ((wm * 32 + (lane & 15)) * APADH + (lane >> 4) * 8) * 2;
    uint32_t kOff = ((wn * 32 + (lane & 7)) * APADH + ((lane >> 3) & 1) * 8) * 2;
    uint32_t pA   = psB + ((wm2 * 16 + (lane & 15)) * PPADH + (lane >> 4) * 8) * 2;
    uint32_t vA   = vsB + (((lane & 7) + ((lane >> 3) & 1) * 8) * APADH) * 2;

#define KSTAGE(buf, kt)                                                          \
    do {                                                                         \
        _Pragma("unroll")                                                        \
        for (int i = 0; i < 4; i++) {                                            \
            int idx = tid + i * 256;                                             \
            int r = idx >> 3, c8 = (idx & 7) * 8;                                \
            cpa16(ksB + ((buf) * 128 * APADH + r * APADH + c8) * 2,              \
                  Kb + (size_t)((kt) * 128 + r) * DD + c8);                      \
        }                                                                        \
        cp_commit();                                                             \
    } while (0)

#define VSTAGE(kt)                                                               \
    do {                                                                         \
        _Pragma("unroll")                                                        \
        for (int i = 0; i < 4; i++) {                                            \
            int idx = tid + i * 256;                                             \
            int r = idx >> 3, c8 = (idx & 7) * 8;                                \
            cpa16(vsB + (r * APADH + c8) * 2,                                    \
                  Vb + (size_t)((kt) * 128 + r) * DD + c8);                      \
        }                                                                        \
        cp_commit();                                                             \
    } while (0)

    // Stage Q tile (fp16, prescaled by 0.125 upstream): 64 rows x 64 cols.
#pragma unroll
    for (int i = 0; i < 2; i++) {
        int idx = tid + i * 256;
        int r = idx >> 3, c8 = (idx & 7) * 8;
        cpa16(qsB + (r * APADH + c8) * 2, Qb + (size_t)(q0 + r) * DD + c8);
    }
    cp_commit();
    cp_wait0();
    __syncthreads();

    uint32_t qf[4][2][4];   // [ks][mi][frag] — Q resident, 32 regs
#pragma unroll
    for (int ks = 0; ks < 4; ks++)
#pragma unroll
        for (int mi = 0; mi < 2; mi++)
            ldsm4(qf[ks][mi], qA + (mi * 16 * APADH + ks * 16) * 2);

    // ---------------- Pass 1: row sums of exp(S) ----------------
    float rs[4] = {};
    KSTAGE(0, 0);
    for (int kt = 0; kt < 16; kt++) {
        if (kt < 15) { KSTAGE((kt + 1) & 1, kt + 1); cp_wait1(); }
        else         { cp_wait0(); }
        __syncthreads();
        uint32_t kbase = ksB + (kt & 1) * 128 * APADH * 2 + kOff;
        float acc[2][4][4] = {};
#pragma unroll
        for (int ks = 0; ks < 4; ks++) {
            uint32_t bf[4][2];
#pragma unroll
            for (int ni = 0; ni < 4; ni++)
                ldsm2(bf[ni], kbase + (ni * 8 * APADH + ks * 16) * 2);
#pragma unroll
            for (int mi = 0; mi < 2; mi++)
#pragma unroll
                for (int ni = 0; ni < 4; ni++)
                    mma16(acc[mi][ni], qf[ks][mi], bf[ni]);
        }
#pragma unroll
        for (int mi = 0; mi < 2; mi++)
#pragma unroll
            for (int ni = 0; ni < 4; ni++) {
                rs[mi * 2 + 0] += __expf(acc[mi][ni][0]) + __expf(acc[mi][ni][1]);
                rs[mi * 2 + 1] += __expf(acc[mi][ni][2]) + __expf(acc[mi][ni][3]);
            }
        __syncthreads();
    }
    // Deterministic cross-warp row-sum reduction.
#pragma unroll
    for (int j = 0; j < 4; j++) {
        float v = rs[j];
        v += __shfl_xor_sync(0xffffffffu, v, 1);
        v += __shfl_xor_sync(0xffffffffu, v, 2);
        if (tig == 0)
            part[wn * QROWS + wm * 32 + (j >> 1) * 16 + g + (j & 1) * 8] = v;
    }
    __syncthreads();
    if (tid < QROWS)
        rinv[tid] = 1.0f / (part[tid] + part[QROWS + tid] +
                            part[2 * QROWS + tid] + part[3 * QROWS + tid]);
    __syncthreads();

    // ---------------- Pass 2: P out + P*V ----------------
    float acc_o[4][4] = {};
    KSTAGE(0, 0);
    for (int kt = 0; kt < 16; kt++) {
        if (kt < 15) KSTAGE((kt + 1) & 1, kt + 1);
        VSTAGE(kt);
        if (kt < 15) cp_wait2(); else cp_wait1();   // K(kt) ready
        __syncthreads();
        uint32_t kbase = ksB + (kt & 1) * 128 * APADH * 2 + kOff;
        float acc[2][4][4] = {};
#pragma unroll
        for (int ks = 0; ks < 4; ks++) {
            uint32_t bf[4][2];
#pragma unroll
            for (int ni = 0; ni < 4; ni++)
                ldsm2(bf[ni], kbase + (ni * 8 * APADH + ks * 16) * 2);
#pragma unroll
            for (int mi = 0; mi < 2; mi++)
#pragma unroll
                for (int ni = 0; ni < 4; ni++)
                    mma16(acc[mi][ni], qf[ks][mi], bf[ni]);
        }
        // Normalize, emit P to gmem (fp32, streaming) and smem (fp16).
#pragma unroll
        for (int mi = 0; mi < 2; mi++) {
            int rl = wm * 32 + mi * 16 + g;
            float ri0 = rinv[rl], ri1 = rinv[rl + 8];
#pragma unroll
            for (int ni = 0; ni < 4; ni++) {
                int cl = wn * 32 + ni * 8 + tig * 2;
                float p0 = __expf(acc[mi][ni][0]) * ri0;
                float p1 = __expf(acc[mi][ni][1]) * ri0;
                float p2 = __expf(acc[mi][ni][2]) * ri1;
                float p3 = __expf(acc[mi][ni][3]) * ri1;
                stcs2(outP + (size_t)(q0 + rl) * NK + kt * 128 + cl, p0, p1);
                stcs2(outP + (size_t)(q0 + rl + 8) * NK + kt * 128 + cl, p2, p3);
                *(uint32_t*)(Ps + rl * PPADH + cl) = packh2(p0, p1);
                *(uint32_t*)(Ps + (rl + 8) * PPADH + cl) = packh2(p2, p3);
            }
        }
        if (kt < 15) cp_wait1(); else cp_wait0();   // V(kt) ready
        __syncthreads();                            // Ps + Vs visible
        // O += P(64x128) * V(128x64): 4x2 warp grid, 16x32 tiles
#pragma unroll
        for (int ks = 0; ks < 8; ks++) {
            int k0 = ks * 16;
            uint32_t a[4], bf[4][2];
            ldsm4(a, pA + k0 * 2);
#pragma unroll
            for (int ni = 0; ni < 4; ni++) {
                int nb = wn2 * 32 + ni * 8;
                ldsm2t(bf[ni], vA + (k0 * APADH + nb) * 2);
            }
#pragma unroll
            for (int ni = 0; ni < 4; ni++)
                mma16(acc_o[ni], a, bf[ni]);
        }
        __syncthreads();
    }
#undef KSTAGE
#undef VSTAGE

    // Write O as fp16 (consumed by the fp16 out-projection GEMM).
    {
        int r = q0 + wm2 * 16 + g;
#pragma unroll
        for (int ni = 0; ni < 4; ni++) {
            int c = wn2 * 32 + ni * 8 + tig * 2;
            __half* o0 = O + ((size_t)b * NQ + r) * DD + h * HDIM + c;
            *(uint32_t*)o0 = packh2(acc_o[ni][0], acc_o[ni][1]);
            __half* o1 = O + ((size_t)b * NQ + r + 8) * DD + h * HDIM + c;
            *(uint32_t*)o1 = packh2(acc_o[ni][2], acc_o[ni][3]);
        }
    }
}

// ---------------------------------------------------------------------------
extern "C" void kernel_launch(void* const* d_in, const int* in_sizes, int n_in,
                              void* d_out, int out_size) {
    const float* q_seq   = (const float*)d_in[0];
    const float* kv_seq  = (const float*)d_in[1];
    const float* Wq      = (const float*)d_in[2];
    const float* bq      = (const float*)d_in[3];
    const float* Wk      = (const float*)d_in[4];
    const float* bk      = (const float*)d_in[5];
    const float* Wv      = (const float*)d_in[6];
    const float* bv      = (const float*)d_in[7];
    const float* Wo      = (const float*)d_in[8];
    const float* bo      = (const float*)d_in[9];
    const float* freqs_q = (const float*)d_in[10];
    const float* freqs_kv= (const float*)d_in[11];

    float* out  = (float*)d_out;
    float* attn = out + (size_t)BB * NQ * DD;

    __half *gQ, *gK, *gV, *gO, *gXq, *gXkv, *gWq, *gWk, *gWv, *gWo;
    cudaGetSymbolAddress((void**)&gQ,  g_Q);
    cudaGetSymbolAddress((void**)&gK,  g_K);
    cudaGetSymbolAddress((void**)&gV,  g_V);
    cudaGetSymbolAddress((void**)&gO,  g_O);
    cudaGetSymbolAddress((void**)&gXq, g_Xq);
    cudaGetSymbolAddress((void**)&gXkv,g_Xkv);
    cudaGetSymbolAddress((void**)&gWq, g_Wq);
    cudaGetSymbolAddress((void**)&gWk, g_Wk);
    cudaGetSymbolAddress((void**)&gWv, g_Wv);
    cudaGetSymbolAddress((void**)&gWo, g_Wo);

    static int attr_done = 0;
    if (!attr_done) {
        cudaFuncSetAttribute(gemm_bias_rope_tc,
                             cudaFuncAttributeMaxDynamicSharedMemorySize, GEMM_SMEM);
        cudaFuncSetAttribute(attn_fused,
                             cudaFuncAttributeMaxDynamicSharedMemorySize, ATTN_SMEM);
        attr_done = 1;
    }

    // Pre-convert fp32 inputs to fp16 once.
    const int SEQ4 = (BB * NQ * DD) / 4;
    const int W4   = (DD * DD) / 4;
    cvt_f16_kernel<<<(SEQ4 + 255) / 256, 256>>>((const float4*)q_seq,  (uint2*)gXq,  SEQ4);
    cvt_f16_kernel<<<(SEQ4 + 255) / 256, 256>>>((const float4*)kv_seq, (uint2*)gXkv, SEQ4);
    cvt_f16_kernel<<<(W4 + 255) / 256, 256>>>((const float4*)Wq, (uint2*)gWq, W4);
    cvt_f16_kernel<<<(W4 + 255) / 256, 256>>>((const float4*)Wk, (uint2*)gWk, W4);
    cvt_f16_kernel<<<(W4 + 255) / 256, 256>>>((const float4*)Wv, (uint2*)gWv, W4);
    cvt_f16_kernel<<<(W4 + 255) / 256, 256>>>((const float4*)Wo, (uint2*)gWo, W4);

    dim3 gproj(DD / GBN, (BB * NQ) / GBM);   // 8 x 16 = 128 blocks

    gemm_bias_rope_tc<<<gproj, 256, GEMM_SMEM>>>(
        gXq, gWq, bq, gQ, BB * NQ, DD, DD, freqs_q, (float)(2 * NQ), 1.0f, 1, 1, 0.125f);
    gemm_bias_rope_tc<<<gproj, 256, GEMM_SMEM>>>(
        gXkv, gWk, bk, gK, BB * NK, DD, DD, freqs_kv, (float)(2 * NK), -1.0f, 1, 1, 1.0f);
    gemm_bias_rope_tc<<<gproj, 256, GEMM_SMEM>>>(
        gXkv, gWv, bv, gV, BB * NK, DD, DD, nullptr, 1.0f, 0.0f, 0, 1, 1.0f);

    attn_fused<<<dim3(NQ / QROWS, BB * HH), 256, ATTN_SMEM>>>(gQ, gK, gV, attn, gO);

    gemm_bias_rope_tc<<<gproj, 256, GEMM_SMEM>>>(
        gO, gWo, bo, out, BB * NQ, DD, DD, nullptr, 1.0f, 0.0f, 0, 0, 1.0f);
}

// round 15
// speedup vs baseline: 2.0111x; 1.2135x over previous
#include <cuda_runtime.h>
#include <cuda_fp16.h>
#include <math.h>
#include <stdint.h>

#define BB 2
#define NQ 2048
#define NK 2048
#define DD 1024
#define HH 16
#define HDIM 64

// Scratch (allocation-free: __device__ globals), all fp16 at rest.
__device__ __half g_Q[(size_t)BB * NQ * DD];
__device__ __half g_K[(size_t)BB * NK * DD];
__device__ __half g_V[(size_t)BB * NK * DD];
__device__ __half g_O[(size_t)BB * NQ * DD];
__device__ __half g_Xq[(size_t)BB * NQ * DD];
__device__ __half g_Xkv[(size_t)BB * NK * DD];
__device__ __half g_Wq[(size_t)DD * DD];
__device__ __half g_Wk[(size_t)DD * DD];
__device__ __half g_Wv[(size_t)DD * DD];
__device__ __half g_Wo[(size_t)DD * DD];

// ---------------------------------------------------------------------------
// helpers
// ---------------------------------------------------------------------------
__device__ __forceinline__ uint32_t packh2(float a, float b) {
    __half2 h = __floats2half2_rn(a, b);
    return *(uint32_t*)&h;
}

__device__ __forceinline__ void mma16(float c[4], const uint32_t a[4], const uint32_t b[2]) {
    asm volatile(
        "mma.sync.aligned.m16n8k16.row.col.f32.f16.f16.f32 "
        "{%0,%1,%2,%3}, {%4,%5,%6,%7}, {%8,%9}, {%0,%1,%2,%3};\n"
        : "+f"(c[0]), "+f"(c[1]), "+f"(c[2]), "+f"(c[3])
        : "r"(a[0]), "r"(a[1]), "r"(a[2]), "r"(a[3]), "r"(b[0]), "r"(b[1]));
}

__device__ __forceinline__ void ldsm4(uint32_t a[4], uint32_t addr) {
    asm volatile("ldmatrix.sync.aligned.m8n8.x4.shared.b16 {%0,%1,%2,%3}, [%4];"
                 : "=r"(a[0]), "=r"(a[1]), "=r"(a[2]), "=r"(a[3]) : "r"(addr));
}
__device__ __forceinline__ void ldsm2(uint32_t b[2], uint32_t addr) {
    asm volatile("ldmatrix.sync.aligned.m8n8.x2.shared.b16 {%0,%1}, [%2];"
                 : "=r"(b[0]), "=r"(b[1]) : "r"(addr));
}
__device__ __forceinline__ void ldsm2t(uint32_t b[2], uint32_t addr) {
    asm volatile("ldmatrix.sync.aligned.m8n8.x2.trans.shared.b16 {%0,%1}, [%2];"
                 : "=r"(b[0]), "=r"(b[1]) : "r"(addr));
}

__device__ __forceinline__ void cpa16(uint32_t dst_smem, const void* src) {
    asm volatile("cp.async.cg.shared.global [%0], [%1], 16;\n" :: "r"(dst_smem), "l"(src));
}
__device__ __forceinline__ void cp_commit() {
    asm volatile("cp.async.commit_group;\n");
}
__device__ __forceinline__ void cp_wait0() { asm volatile("cp.async.wait_group 0;\n"); }
__device__ __forceinline__ void cp_wait1() { asm volatile("cp.async.wait_group 1;\n"); }
__device__ __forceinline__ void cp_wait2() { asm volatile("cp.async.wait_group 2;\n"); }

__device__ __forceinline__ void stcs2(float* p, float a, float b) {
    asm volatile("st.global.cs.v2.f32 [%0], {%1,%2};\n" :: "l"(p), "f"(a), "f"(b));
}

extern __shared__ char smraw[];

// ---------------------------------------------------------------------------
// Fused fp32 -> fp16 converter for all 6 inputs (one launch).
// ---------------------------------------------------------------------------
#define SEQ4 ((BB * NQ * DD) / 4)
#define W4   ((DD * DD) / 4)
#define CVT_TOTAL (2 * SEQ4 + 4 * W4)

__global__ void cvt_all_kernel(const float4* q, const float4* kv,
                               const float4* w0, const float4* w1,
                               const float4* w2, const float4* w3,
                               uint2* dq, uint2* dkv,
                               uint2* dw0, uint2* dw1, uint2* dw2, uint2* dw3) {
    int i = blockIdx.x * blockDim.x + threadIdx.x;
    if (i >= CVT_TOTAL) return;
    const float4* s; uint2* d; int off;
    if (i < SEQ4)            { s = q;  d = dq;  off = i; }
    else if (i < 2 * SEQ4)   { s = kv; d = dkv; off = i - SEQ4; }
    else {
        int j = i - 2 * SEQ4;
        int w = j / W4; off = j - w * W4;
        s = (w == 0) ? w0 : (w == 1) ? w1 : (w == 2) ? w2 : w3;
        d = (w == 0) ? dw0 : (w == 1) ? dw1 : (w == 2) ? dw2 : dw3;
    }
    float4 v = s[off];
    d[off] = make_uint2(packh2(v.x, v.y), packh2(v.z, v.w));
}

// ---------------------------------------------------------------------------
// Tensor-core GEMM (fp16 in, fp32 acc) + optional fused xpos-RoPE epilogue.
// 128x128 tile (256 blocks = 1 full wave @ 2 CTAs/SM), k-tile 64,
// cp.async double-buffered, 8 warps 2x4, warp tile 64x32.
// ---------------------------------------------------------------------------
#define GBM 128
#define GBN 128
#define GBK 64
#define GPADH 72
#define GEMM_SMEM (2 * (GBM * GPADH + GBN * GPADH) * 2)   // 73728

__global__ void __launch_bounds__(256, 2)
gemm_bias_rope_tc(const __half* __restrict__ X, const __half* __restrict__ W,
                  const float* __restrict__ bias, void* __restrict__ Yout,
                  int M, int N, int K,
                  const float* __restrict__ freqs, float scale_base, float rsign,
                  int do_rope, int out_f16, float prescale) {
    int tid = threadIdx.x;
    int warp = tid >> 5, lane = tid & 31;
    int g = lane >> 2, tig = lane & 3;
    int wm = warp >> 2, wn = warp & 3;     // 2 x 4 warps, tile 64x32
    int row0 = blockIdx.y * GBM, col0 = blockIdx.x * GBN;

    uint32_t xsB = (uint32_t)__cvta_generic_to_shared(smraw);
    uint32_t wsB = xsB + 2 * GBM * GPADH * 2;

    uint32_t aOff = ((wm * 64 + (lane & 15)) * GPADH + (lane >> 4) * 8) * 2;
    uint32_t bOff = ((wn * 32 + (lane & 7)) * GPADH + ((lane >> 3) & 1) * 8) * 2;

    float acc[4][4][4] = {};

#define GSTAGE(buf, kt)                                                          \
    do {                                                                         \
        _Pragma("unroll")                                                        \
        for (int i = 0; i < 4; i++) {                                            \
            int idx = tid + i * 256;                                             \
            int r = idx >> 3, c8 = (idx & 7) * 8;                                \
            cpa16(xsB + ((buf) * GBM * GPADH + r * GPADH + c8) * 2,              \
                  X + (size_t)(row0 + r) * K + (kt) + c8);                       \
        }                                                                        \
        _Pragma("unroll")                                                        \
        for (int i = 0; i < 4; i++) {                                            \
            int idx = tid + i * 256;                                             \
            int r = idx >> 3, c8 = (idx & 7) * 8;                                \
            cpa16(wsB + ((buf) * GBN * GPADH + r * GPADH + c8) * 2,              \
                  W + (size_t)(col0 + r) * K + (kt) + c8);                       \
        }                                                                        \
        cp_commit();                                                             \
    } while (0)

    GSTAGE(0, 0);
    int T = K / GBK;
    for (int t = 0; t < T; t++) {
        if (t + 1 < T) { GSTAGE((t + 1) & 1, (t + 1) * GBK); cp_wait1(); }
        else           { cp_wait0(); }
        __syncthreads();
        uint32_t xb = xsB + (t & 1) * GBM * GPADH * 2 + aOff;
        uint32_t wb = wsB + (t & 1) * GBN * GPADH * 2 + bOff;
#pragma unroll
        for (int ks = 0; ks < 4; ks++) {
            int k0 = ks * 16;
            uint32_t a[4][4], bf[4][2];
#pragma unroll
            for (int mi = 0; mi < 4; mi++)
                ldsm4(a[mi], xb + (mi * 16 * GPADH + k0) * 2);
#pragma unroll
            for (int ni = 0; ni < 4; ni++)
                ldsm2(bf[ni], wb + (ni * 8 * GPADH + k0) * 2);
#pragma unroll
            for (int mi = 0; mi < 4; mi++)
#pragma unroll
                for (int ni = 0; ni < 4; ni++)
                    mma16(acc[mi][ni], a[mi], bf[ni]);
        }
        __syncthreads();
    }
#undef GSTAGE

#pragma unroll
    for (int mi = 0; mi < 4; mi++) {
        int r = row0 + wm * 64 + mi * 16 + g;
#pragma unroll
        for (int ni = 0; ni < 4; ni++) {
            int c = col0 + wn * 32 + ni * 8 + tig * 2;
            float v0 = acc[mi][ni][0] + bias[c];
            float v1 = acc[mi][ni][1] + bias[c + 1];
            float v2 = acc[mi][ni][2] + bias[c];
            float v3 = acc[mi][ni][3] + bias[c + 1];
            if (do_rope) {
                int cd = c & (HDIM - 1);
                float f = freqs[cd >> 1];
                float sv = ((float)cd + 0.4f * (float)HDIM) / (1.4f * (float)HDIM);
                {
                    float n0 = (float)(r & (NQ - 1));
                    float sn, cs; sincosf(n0 * f, &sn, &cs);
                    float scale = powf(sv, (n0 - (float)(NQ / 2)) / scale_base * rsign);
                    float o0 = (v0 * cs - v1 * sn) * scale;
                    float o1 = (v1 * cs + v0 * sn) * scale;
                    v0 = o0; v1 = o1;
                }
                {
                    float n1 = (float)((r + 8) & (NQ - 1));
                    float sn, cs; sincosf(n1 * f, &sn, &cs);
                    float scale = powf(sv, (n1 - (float)(NQ / 2)) / scale_base * rsign);
                    float o2 = (v2 * cs - v3 * sn) * scale;
                    float o3 = (v3 * cs + v2 * sn) * scale;
                    v2 = o2; v3 = o3;
                }
            }
            if (out_f16) {
                __half* Y = (__half*)Yout;
                *(uint32_t*)(Y + (size_t)r * N + c) = packh2(v0 * prescale, v1 * prescale);
                *(uint32_t*)(Y + (size_t)(r + 8) * N + c) = packh2(v2 * prescale, v3 * prescale);
            } else {
                float* Y = (float*)Yout;
                *(float2*)(Y + (size_t)r * N + c) = make_float2(v0, v1);
                *(float2*)(Y + (size_t)(r + 8) * N + c) = make_float2(v2, v3);
            }
        }
    }
}

// ---------------------------------------------------------------------------
// Fused attention: 64-row q-tiles, 64-row k-tiles, 3 CTAs/SM.
// 256 threads. S: 2x4 warp grid (32x16 tiles); PV: 4x2 (16x32 tiles).
// Q fragments register-resident; K/P via ldmatrix; V via ldmatrix.trans.
// ---------------------------------------------------------------------------
#define QROWS 64
#define KT 64
#define NKT (NK / KT)          // 32
#define APADH 72
#define PPADH 72
#define OQ_B 0
#define OK_B (QROWS * APADH * 2)                 // 9216
#define OV_B (OK_B + 2 * KT * APADH * 2)         // 27648
#define OP_B (OV_B + KT * APADH * 2)             // 36864
#define OPART_B (OP_B + QROWS * PPADH * 2)       // 46080
#define ORINV_B (OPART_B + 4 * QROWS * 4)        // 47104
#define ATTN_SMEM (ORINV_B + QROWS * 4)          // 47360 (x3 = 139 KB/SM)

__global__ void __launch_bounds__(256, 3)
attn_fused(const __half* __restrict__ Q, const __half* __restrict__ Kg,
           const __half* __restrict__ Vg, float* __restrict__ attn,
           __half* __restrict__ O) {
    char* smb = smraw;
    __half* Ps = (__half*)(smb + OP_B);
    float* part = (float*)(smb + OPART_B);  // [4][64]
    float* rinv = (float*)(smb + ORINV_B);  // [64]

    int bh = blockIdx.y;
    int b = bh / HH, h = bh % HH;
    int q0 = blockIdx.x * QROWS;
    const __half* Qb = Q + (size_t)b * NQ * DD + h * HDIM;
    const __half* Kb = Kg + (size_t)b * NK * DD + h * HDIM;
    const __half* Vb = Vg + (size_t)b * NK * DD + h * HDIM;
    float* outP = attn + (size_t)bh * NQ * NK;

    int tid = threadIdx.x;
    int warp = tid >> 5, lane = tid & 31;
    int g = lane >> 2, tig = lane & 3;
    int wm = warp >> 2, wn = warp & 3;      // 2x4 (S): 32x16 warp tiles
    int wm2 = warp >> 1, wn2 = warp & 1;    // 4x2 (PV): 16x32 warp tiles

    uint32_t smB = (uint32_t)__cvta_generic_to_shared(smb);
    uint32_t qsB = smB + OQ_B;
    uint32_t ksB = smB + OK_B;
    uint32_t vsB = smB + OV_B;
    uint32_t psB = smB + OP_B;

    uint32_t qA   = qsB + ((wm * 32 + (lane & 15)) * APADH + (lane >> 4) * 8) * 2;
    uint32_t kOff = ((wn * 16 + (lane & 7)) * APADH + ((lane >> 3) & 1) * 8) * 2;
    uint32_t pA   = psB + ((wm2 * 16 + (lane & 15)) * PPADH + (lane >> 4) * 8) * 2;
    uint32_t vA   = vsB + (((lane & 7) + ((lane >> 3) & 1) * 8) * APADH) * 2;

#define KSTAGE(buf, kt)                                                          \
    do {                                                                         \
        _Pragma("unroll")                                                        \
        for (int i = 0; i < 2; i++) {                                            \
            int idx = tid + i * 256;                                             \
            int r = idx >> 3, c8 = (idx & 7) * 8;                                \
            cpa16(ksB + ((buf) * KT * APADH + r * APADH + c8) * 2,               \
                  Kb + (size_t)((kt) * KT + r) * DD + c8);                       \
        }                                                                        \
        cp_commit();                                                             \
    } while (0)

#define VSTAGE(kt)                                                               \
    do {                                                                         \
        _Pragma("unroll")                                                        \
        for (int i = 0; i < 2; i++) {                                            \
            int idx = tid + i * 256;                                             \
            int r = idx >> 3, c8 = (idx & 7) * 8;                                \
            cpa16(vsB + (r * APADH + c8) * 2,                                    \
                  Vb + (size_t)((kt) * KT + r) * DD + c8);                       \
        }                                                                        \
        cp_commit();                                                             \
    } while (0)

    // Stage Q tile (fp16, prescaled by 0.125 upstream): 64 rows x 64 cols.
#pragma unroll
    for (int i = 0; i < 2; i++) {
        int idx = tid + i * 256;
        int r = idx >> 3, c8 = (idx & 7) * 8;
        cpa16(qsB + (r * APADH + c8) * 2, Qb + (size_t)(q0 + r) * DD + c8);
    }
    cp_commit();
    cp_wait0();
    __syncthreads();

    uint32_t qf[4][2][4];   // [ks][mi][frag] — Q resident, 32 regs
#pragma unroll
    for (int ks = 0; ks < 4; ks++)
#pragma unroll
        for (int mi = 0; mi < 2; mi++)
            ldsm4(qf[ks][mi], qA + (mi * 16 * APADH + ks * 16) * 2);

    // ---------------- Pass 1: row sums of exp(S) ----------------
    float rs[4] = {};
    KSTAGE(0, 0);
    for (int kt = 0; kt < NKT; kt++) {
        if (kt < NKT - 1) { KSTAGE((kt + 1) & 1, kt + 1); cp_wait1(); }
        else              { cp_wait0(); }
        __syncthreads();
        uint32_t kbase = ksB + (kt & 1) * KT * APADH * 2 + kOff;
        float acc[2][2][4] = {};
#pragma unroll
        for (int ks = 0; ks < 4; ks++) {
            uint32_t bf[2][2];
#pragma unroll
            for (int ni = 0; ni < 2; ni++)
                ldsm2(bf[ni], kbase + (ni * 8 * APADH + ks * 16) * 2);
#pragma unroll
            for (int mi = 0; mi < 2; mi++)
#pragma unroll
                for (int ni = 0; ni < 2; ni++)
                    mma16(acc[mi][ni], qf[ks][mi], bf[ni]);
        }
#pragma unroll
        for (int mi = 0; mi < 2; mi++)
#pragma unroll
            for (int ni = 0; ni < 2; ni++) {
                rs[mi * 2 + 0] += __expf(acc[mi][ni][0]) + __expf(acc[mi][ni][1]);
                rs[mi * 2 + 1] += __expf(acc[mi][ni][2]) + __expf(acc[mi][ni][3]);
            }
        __syncthreads();
    }
    // Deterministic cross-warp row-sum reduction.
#pragma unroll
    for (int j = 0; j < 4; j++) {
        float v = rs[j];
        v += __shfl_xor_sync(0xffffffffu, v, 1);
        v += __shfl_xor_sync(0xffffffffu, v, 2);
        if (tig == 0)
            part[wn * QROWS + wm * 32 + (j >> 1) * 16 + g + (j & 1) * 8] = v;
    }
    __syncthreads();
    if (tid < QROWS)
        rinv[tid] = 1.0f / (part[tid] + part[QROWS + tid] +
                            part[2 * QROWS + tid] + part[3 * QROWS + tid]);
    __syncthreads();

    // ---------------- Pass 2: P out + P*V ----------------
    float acc_o[4][4] = {};
    KSTAGE(0, 0);
    for (int kt = 0; kt < NKT; kt++) {
        if (kt < NKT - 1) KSTAGE((kt + 1) & 1, kt + 1);
        VSTAGE(kt);
        if (kt < NKT - 1) cp_wait2(); else cp_wait1();   // K(kt) ready
        __syncthreads();
        uint32_t kbase = ksB + (kt & 1) * KT * APADH * 2 + kOff;
        float acc[2][2][4] = {};
#pragma unroll
        for (int ks = 0; ks < 4; ks++) {
            uint32_t bf[2][2];
#pragma unroll
            for (int ni = 0; ni < 2; ni++)
                ldsm2(bf[ni], kbase + (ni * 8 * APADH + ks * 16) * 2);
#pragma unroll
            for (int mi = 0; mi < 2; mi++)
#pragma unroll
                for (int ni = 0; ni < 2; ni++)
                    mma16(acc[mi][ni], qf[ks][mi], bf[ni]);
        }
        // Normalize, emit P to gmem (fp32, streaming) and smem (fp16).
#pragma unroll
        for (int mi = 0; mi < 2; mi++) {
            int rl = wm * 32 + mi * 16 + g;
            float ri0 = rinv[rl], ri1 = rinv[rl + 8];
#pragma unroll
            for (int ni = 0; ni < 2; ni++) {
                int cl = wn * 16 + ni * 8 + tig * 2;
                float p0 = __expf(acc[mi][ni][0]) * ri0;
                float p1 = __expf(acc[mi][ni][1]) * ri0;
                float p2 = __expf(acc[mi][ni][2]) * ri1;
                float p3 = __expf(acc[mi][ni][3]) * ri1;
                stcs2(outP + (size_t)(q0 + rl) * NK + kt * KT + cl, p0, p1);
                stcs2(outP + (size_t)(q0 + rl + 8) * NK + kt * KT + cl, p2, p3);
                *(uint32_t*)(Ps + rl * PPADH + cl) = packh2(p0, p1);
                *(uint32_t*)(Ps + (rl + 8) * PPADH + cl) = packh2(p2, p3);
            }
        }
        if (kt < NKT - 1) cp_wait1(); else cp_wait0();   // V(kt) ready
        __syncthreads();                                 // Ps + Vs visible
        // O += P(64x64) * V(64x64): 4x2 warp grid, 16x32 tiles
#pragma unroll
        for (int ks = 0; ks < 4; ks++) {
            int k0 = ks * 16;
            uint32_t a[4], bf[4][2];
            ldsm4(a, pA + k0 * 2);
#pragma unroll
            for (int ni = 0; ni < 4; ni++) {
                int nb = wn2 * 32 + ni * 8;
                ldsm2t(bf[ni], vA + (k0 * APADH + nb) * 2);
            }
#pragma unroll
            for (int ni = 0; ni < 4; ni++)
                mma16(acc_o[ni], a, bf[ni]);
        }
        __syncthreads();
    }
#undef KSTAGE
#undef VSTAGE

    // Write O as fp16 (consumed by the fp16 out-projection GEMM).
    {
        int r = q0 + wm2 * 16 + g;
#pragma unroll
        for (int ni = 0; ni < 4; ni++) {
            int c = wn2 * 32 + ni * 8 + tig * 2;
            __half* o0 = O + ((size_t)b * NQ + r) * DD + h * HDIM + c;
            *(uint32_t*)o0 = packh2(acc_o[ni][0], acc_o[ni][1]);
            __half* o1 = O + ((size_t)b * NQ + r + 8) * DD + h * HDIM + c;
            *(uint32_t*)o1 = packh2(acc_o[ni][2], acc_o[ni][3]);
        }
    }
}

// ---------------------------------------------------------------------------
extern "C" void kernel_launch(void* const* d_in, const int* in_sizes, int n_in,
                              void* d_out, int out_size) {
    const float* q_seq   = (const float*)d_in[0];
    const float* kv_seq  = (const float*)d_in[1];
    const float* Wq      = (const float*)d_in[2];
    const float* bq      = (const float*)d_in[3];
    const float* Wk      = (const float*)d_in[4];
    const float* bk      = (const float*)d_in[5];
    const float* Wv      = (const float*)d_in[6];
    const float* bv      = (const float*)d_in[7];
    const float* Wo      = (const float*)d_in[8];
    const float* bo      = (const float*)d_in[9];
    const float* freqs_q = (const float*)d_in[10];
    const float* freqs_kv= (const float*)d_in[11];

    float* out  = (float*)d_out;
    float* attn = out + (size_t)BB * NQ * DD;

    __half *gQ, *gK, *gV, *gO, *gXq, *gXkv, *gWq, *gWk, *gWv, *gWo;
    cudaGetSymbolAddress((void**)&gQ,  g_Q);
    cudaGetSymbolAddress((void**)&gK,  g_K);
    cudaGetSymbolAddress((void**)&gV,  g_V);
    cudaGetSymbolAddress((void**)&gO,  g_O);
    cudaGetSymbolAddress((void**)&gXq, g_Xq);
    cudaGetSymbolAddress((void**)&gXkv,g_Xkv);
    cudaGetSymbolAddress((void**)&gWq, g_Wq);
    cudaGetSymbolAddress((void**)&gWk, g_Wk);
    cudaGetSymbolAddress((void**)&gWv, g_Wv);
    cudaGetSymbolAddress((void**)&gWo, g_Wo);

    static int attr_done = 0;
    if (!attr_done) {
        cudaFuncSetAttribute(gemm_bias_rope_tc,
                             cudaFuncAttributeMaxDynamicSharedMemorySize, GEMM_SMEM);
        cudaFuncSetAttribute(attn_fused,
                             cudaFuncAttributeMaxDynamicSharedMemorySize, ATTN_SMEM);
        attr_done = 1;
    }

    // Single fused pre-convert launch.
    cvt_all_kernel<<<(CVT_TOTAL + 255) / 256, 256>>>(
        (const float4*)q_seq, (const float4*)kv_seq,
        (const float4*)Wq, (const float4*)Wk, (const float4*)Wv, (const float4*)Wo,
        (uint2*)gXq, (uint2*)gXkv,
        (uint2*)gWq, (uint2*)gWk, (uint2*)gWv, (uint2*)gWo);

    dim3 gproj(DD / GBN, (BB * NQ) / GBM);   // 8 x 32 = 256 blocks, 2/SM

    gemm_bias_rope_tc<<<gproj, 256, GEMM_SMEM>>>(
        gXq, gWq, bq, gQ, BB * NQ, DD, DD, freqs_q, (float)(2 * NQ), 1.0f, 1, 1, 0.125f);
    gemm_bias_rope_tc<<<gproj, 256, GEMM_SMEM>>>(
        gXkv, gWk, bk, gK, BB * NK, DD, DD, freqs_kv, (float)(2 * NK), -1.0f, 1, 1, 1.0f);
    gemm_bias_rope_tc<<<gproj, 256, GEMM_SMEM>>>(
        gXkv, gWv, bv, gV, BB * NK, DD, DD, nullptr, 1.0f, 0.0f, 0, 1, 1.0f);

    attn_fused<<<dim3(NQ / QROWS, BB * HH), 256, ATTN_SMEM>>>(gQ, gK, gV, attn, gO);

    gemm_bias_rope_tc<<<gproj, 256, GEMM_SMEM>>>(
        gO, gWo, bo, out, BB * NQ, DD, DD, nullptr, 1.0f, 0.0f, 0, 0, 1.0f);
}